// round 13
// baseline (speedup 1.0000x reference)
#include <cuda_runtime.h>
#include <cuda_bf16.h>
#include <mma.h>
#include <cstdint>

using namespace nvcuda;

// ---------------- device scratch (static; no allocations) ----------------
__device__ __nv_bfloat16 g_xln  [2L*16384*1024];
__device__ __nv_bfloat16 g_wqkv [2L*3*1024*1024];
__device__ __nv_bfloat16 g_wo   [2L*1024*1024];
__device__ __nv_bfloat16 g_w1   [2L*1024*4096];
__device__ __nv_bfloat16 g_w2   [2L*4096*1024];
__device__ __nv_bfloat16 g_qkv  [2L*3*16384*1024];
__device__ float         g_Smat [1024L*256*256];
__device__ __nv_bfloat16 g_Pmat [1024L*256*256];
__device__ __nv_bfloat16 g_Omat [2L*16384*1024];
__device__ float         g_att  [2L*16384*1024];
__device__ __nv_bfloat16 g_attln[2L*16384*1024];
__device__ __nv_bfloat16 g_hid  [2L*16384*4096];

// ---------------- helpers ----------------
__device__ __forceinline__ uint32_t smem_u32(const void* p) {
    uint32_t a;
    asm("{ .reg .u64 t; cvta.to.shared.u64 t, %1; cvt.u32.u64 %0, t; }" : "=r"(a) : "l"(p));
    return a;
}
__device__ __forceinline__ void cpa16(uint32_t d, const void* s) {
    asm volatile("cp.async.cg.shared.global [%0], [%1], 16;" :: "r"(d), "l"(s));
}
#define CP_COMMIT() asm volatile("cp.async.commit_group;" ::: "memory")

// ---------------- fused convert (8 regions, one launch) ----------------
struct CvtP {
    const float* s[8];
    __nv_bfloat16* d[8];
    long n[8];
};
__global__ void cvt8_k(CvtP p) {
    int reg = blockIdx.y;
    long i = (long)blockIdx.x * 1024 + threadIdx.x;
    const float* s = p.s[reg];
    __nv_bfloat16* d = p.d[reg];
    long n = p.n[reg];
#pragma unroll
    for (int it = 0; it < 4; ++it) {
        long j = i + (long)it * 256;
        if (j < n) d[j] = __float2bfloat16(s[j]);
    }
}

// ---------------- fused dual LayerNorm ----------------
__global__ void ln2_k(const float* __restrict__ x0, __nv_bfloat16* __restrict__ y0,
                      const float* __restrict__ g0, const float* __restrict__ b0,
                      const float* __restrict__ x1, __nv_bfloat16* __restrict__ y1,
                      const float* __restrict__ g1, const float* __restrict__ b1) {
    const float* x = blockIdx.y ? x1 : x0;
    __nv_bfloat16* y = blockIdx.y ? y1 : y0;
    const float* gam = blockIdx.y ? g1 : g0;
    const float* bet = blockIdx.y ? b1 : b0;
    long row = blockIdx.x;
    const float* xr = x + row * 1024;
    int tid = threadIdx.x;
    float v[4]; float s = 0.f, s2 = 0.f;
#pragma unroll
    for (int i = 0; i < 4; i++) { float t = xr[tid + i*256]; v[i] = t; s += t; s2 += t*t; }
#pragma unroll
    for (int o = 16; o; o >>= 1) {
        s  += __shfl_xor_sync(0xffffffffu, s,  o);
        s2 += __shfl_xor_sync(0xffffffffu, s2, o);
    }
    __shared__ float sh[2][8];
    if ((tid & 31) == 0) { sh[0][tid>>5] = s; sh[1][tid>>5] = s2; }
    __syncthreads();
    float S = 0.f, S2 = 0.f;
#pragma unroll
    for (int w = 0; w < 8; w++) { S += sh[0][w]; S2 += sh[1][w]; }
    float m   = S  * (1.f/1024.f);
    float var = S2 * (1.f/1024.f) - m*m;
    float inv = rsqrtf(var + 1e-5f);
#pragma unroll
    for (int i = 0; i < 4; i++) {
        int c = tid + i*256;
        y[row*1024 + c] = __float2bfloat16((v[i]-m)*inv*gam[c] + bet[c]);
    }
}

__global__ void softmax_k(const float* __restrict__ S, __nv_bfloat16* __restrict__ P) {
    long row = (long)blockIdx.x * 8 + (threadIdx.x >> 5);
    int lane = threadIdx.x & 31;
    const float* sr = S + row * 256;
    float v[8]; float m = -1e30f;
#pragma unroll
    for (int e = 0; e < 8; e++) { v[e] = sr[e*32 + lane]; m = fmaxf(m, v[e]); }
#pragma unroll
    for (int o = 16; o; o >>= 1) m = fmaxf(m, __shfl_xor_sync(0xffffffffu, m, o));
    float s = 0.f;
#pragma unroll
    for (int e = 0; e < 8; e++) { v[e] = __expf(v[e] - m); s += v[e]; }
#pragma unroll
    for (int o = 16; o; o >>= 1) s += __shfl_xor_sync(0xffffffffu, s, o);
    float inv = 1.f / s;
#pragma unroll
    for (int e = 0; e < 8; e++)
        P[row*256 + e*32 + lane] = __float2bfloat16(v[e] * inv);
}

// ---------------- merged GEMM params (up to 6 instances per launch) ----------------
struct GPM {
    const __nv_bfloat16* A[6];
    const __nv_bfloat16* B[6];
    void*                C[6];
    const float*      bias[6];
    const float*     resid[6];
    long lda, ldb, ldc, ldr;
    long sAb, sAh, sBb, sBh, sCb, sCh;
    int  ZG;     // z-slices per instance (= batches*Hh)
    int  Hh;
    int  K;
    const float* coeffs; int ci0base;
    float alpha;
};

// ---------------- pipelined wmma GEMM: 256 thr, BK=64, reg double-buffered ----------------
// EPI: 0 = bf16 store (+opt bias), 1 = fp32 store * alpha,
//      3 = fp32 store: c_res*resid + c_out*(acc+bias), 4 = bf16 gelu(acc+bias)
static const int BM = 128, BN = 128, BK = 64;
static const int STG = 3;
static const int LDA_S  = BK + 8;        // 72 elems = 144 B
static const int LDB_NN = BN + 8;        // 136 elems = 272 B
static const int LDB_NT = BK + 8;        // 72
static const int EPLD   = 20;
static const int A_STG_B   = BM * LDA_S * 2;      // 18432 B
static const int B_STG_NN  = BK * LDB_NN * 2;     // 17408 B
static const int B_STG_NT  = BN * LDB_NT * 2;     // 18432 B
static const int SMEM_NN   = STG * (A_STG_B + B_STG_NN);  // 107520
static const int SMEM_NT   = STG * (A_STG_B + B_STG_NT);  // 110592

template <int EPI, bool TB>
__global__ void __launch_bounds__(256) gemm_k(GPM p) {
    extern __shared__ char dsm[];
    const int tid  = threadIdx.x;
    const int warp = tid >> 5, lane = tid & 31;
    const int wm = warp >> 2, wn = warp & 3;   // 2x4 warp grid, 64x32 warp tile

    const int zz = blockIdx.z;
    const int g  = zz / p.ZG;
    const int r  = zz - g * p.ZG;
    const int bb = r / p.Hh, hh = r - bb * p.Hh;
    const __nv_bfloat16* Ab = p.A[g] + (long)bb * p.sAb + (long)hh * p.sAh;
    const __nv_bfloat16* Bb = p.B[g] + (long)bb * p.sBb + (long)hh * p.sBh;
    void* Cp = p.C[g];
    const float* bias = p.bias[g];
    const float* resid = p.resid[g];
    const long coff = (long)bb * p.sCb + (long)hh * p.sCh;

    const int row0 = blockIdx.y * BM;
    const int col0 = blockIdx.x * BN;
    const long lda = p.lda, ldb = p.ldb;

    const uint32_t asb = smem_u32(dsm);
    const uint32_t bsb = asb + STG * A_STG_B;
    __nv_bfloat16* As = (__nv_bfloat16*)dsm;
    __nv_bfloat16* Bs = (__nv_bfloat16*)(dsm + STG * A_STG_B);

    auto load_stage = [&](int slot, int k0) {
        uint32_t ab = asb + slot * A_STG_B;
#pragma unroll
        for (int it = 0; it < 4; ++it) {
            int id = tid + it*256;
            int rr = id >> 3, c = id & 7;
            cpa16(ab + rr*144 + c*16, Ab + (long)(row0 + rr)*lda + k0 + c*8);
        }
        if (!TB) {
            uint32_t bbp = bsb + slot * B_STG_NN;
#pragma unroll
            for (int it = 0; it < 4; ++it) {
                int id = tid + it*256;
                int rr = id >> 4, c = id & 15;
                cpa16(bbp + rr*272 + c*16, Bb + (long)(k0 + rr)*ldb + col0 + c*8);
            }
        } else {
            uint32_t bbp = bsb + slot * B_STG_NT;
#pragma unroll
            for (int it = 0; it < 4; ++it) {
                int id = tid + it*256;
                int rr = id >> 3, c = id & 7;
                cpa16(bbp + rr*144 + c*16, Bb + (long)(col0 + rr)*ldb + k0 + c*8);
            }
        }
    };

    wmma::fragment<wmma::accumulator, 16, 16, 16, float> acc[4][2];
#pragma unroll
    for (int i = 0; i < 4; i++)
#pragma unroll
        for (int j = 0; j < 2; j++) wmma::fill_fragment(acc[i][j], 0.f);

    wmma::fragment<wmma::matrix_a, 16, 16, 16, __nv_bfloat16, wmma::row_major> fa[2][4];
    wmma::fragment<wmma::matrix_b, 16, 16, 16, __nv_bfloat16, wmma::row_major> fbr[2][2];
    wmma::fragment<wmma::matrix_b, 16, 16, 16, __nv_bfloat16, wmma::col_major> fbc[2][2];

    const int kiters = p.K >> 6;

#pragma unroll
    for (int s = 0; s < STG-1; ++s) {
        if (s < kiters) load_stage(s, s * BK);
        CP_COMMIT();
    }

    for (int k = 0; k < kiters; ++k) {
        asm volatile("cp.async.wait_group %0;" :: "n"(STG-2));
        __syncthreads();
        int pf = k + STG - 1;
        if (pf < kiters) load_stage(pf % STG, pf * BK);
        CP_COMMIT();

        int slot = k % STG;
        __nv_bfloat16* Asl = As + slot * (BM * LDA_S);
        __nv_bfloat16* BslNN = Bs + slot * (BK * LDB_NN);
        __nv_bfloat16* BslNT = Bs + slot * (BN * LDB_NT);

#pragma unroll
        for (int mi = 0; mi < 4; ++mi)
            wmma::load_matrix_sync(fa[0][mi], &Asl[(wm*64 + mi*16)*LDA_S + 0], LDA_S);
        if (!TB) {
#pragma unroll
            for (int ni = 0; ni < 2; ++ni)
                wmma::load_matrix_sync(fbr[0][ni], &BslNN[0*LDB_NN + wn*32 + ni*16], LDB_NN);
        } else {
#pragma unroll
            for (int ni = 0; ni < 2; ++ni)
                wmma::load_matrix_sync(fbc[0][ni], &BslNT[(wn*32 + ni*16)*LDB_NT + 0], LDB_NT);
        }

#pragma unroll
        for (int j = 0; j < 4; ++j) {
            int cur = j & 1, nxt = cur ^ 1;
            if (j < 3) {
                int kk = (j + 1) * 16;
#pragma unroll
                for (int mi = 0; mi < 4; ++mi)
                    wmma::load_matrix_sync(fa[nxt][mi], &Asl[(wm*64 + mi*16)*LDA_S + kk], LDA_S);
                if (!TB) {
#pragma unroll
                    for (int ni = 0; ni < 2; ++ni)
                        wmma::load_matrix_sync(fbr[nxt][ni], &BslNN[kk*LDB_NN + wn*32 + ni*16], LDB_NN);
                } else {
#pragma unroll
                    for (int ni = 0; ni < 2; ++ni)
                        wmma::load_matrix_sync(fbc[nxt][ni], &BslNT[(wn*32 + ni*16)*LDB_NT + kk], LDB_NT);
                }
            }
            if (!TB) {
#pragma unroll
                for (int mi = 0; mi < 4; ++mi)
#pragma unroll
                    for (int ni = 0; ni < 2; ++ni)
                        wmma::mma_sync(acc[mi][ni], fa[cur][mi], fbr[cur][ni], acc[mi][ni]);
            } else {
#pragma unroll
                for (int mi = 0; mi < 4; ++mi)
#pragma unroll
                    for (int ni = 0; ni < 2; ++ni)
                        wmma::mma_sync(acc[mi][ni], fa[cur][mi], fbc[cur][ni], acc[mi][ni]);
            }
        }
    }
    __syncthreads();   // protect smem reuse in epilogue

    // ---------------- epilogue (reuse dsm as staging) ----------------
    float c_res = 0.f, c_out = 0.f;
    if (EPI == 3) {
        c_res = p.coeffs[p.ci0base + 2*g];
        c_out = p.coeffs[p.ci0base + 2*g + 1];
    }
    float* ep = (float*)dsm;
    float* eptr = &ep[warp * 16 * EPLD];
#pragma unroll
    for (int mi = 0; mi < 4; ++mi) {
#pragma unroll
        for (int ni = 0; ni < 2; ++ni) {
            wmma::store_matrix_sync(eptr, acc[mi][ni], EPLD, wmma::mem_row_major);
            __syncwarp();
            int r0 = row0 + wm*64 + mi*16;
            int c0 = col0 + wn*32 + ni*16;
#pragma unroll
            for (int e = 0; e < 8; ++e) {
                int i = e*32 + lane;
                int rr = i >> 4, c = i & 15;
                float v = eptr[rr*EPLD + c];
                long gr = r0 + rr, gc = c0 + c;
                long cidx = coff + gr*p.ldc + gc;
                if (EPI == 0) {
                    if (bias) v += bias[gc];
                    ((__nv_bfloat16*)Cp)[cidx] = __float2bfloat16(v);
                } else if (EPI == 1) {
                    ((float*)Cp)[cidx] = v * p.alpha;
                } else if (EPI == 3) {
                    v += bias[gc];
                    ((float*)Cp)[cidx] = c_res * resid[gr*p.ldr + gc] + c_out * v;
                } else if (EPI == 4) {
                    v += bias[gc];
                    float gl = 0.5f * v * (1.f + erff(v * 0.70710678118654752f));
                    ((__nv_bfloat16*)Cp)[cidx] = __float2bfloat16(gl);
                }
            }
            __syncwarp();
        }
    }
}

// ---------------- host orchestration ----------------
extern "C" void kernel_launch(void* const* d_in, const int* in_sizes, int n_in,
                              void* d_out, int out_size) {
    (void)in_sizes; (void)n_in; (void)out_size;
    const float* rgb    = (const float*)d_in[0];
    const float* irp    = (const float*)d_in[1];
    const float* ln1g   = (const float*)d_in[2];
    const float* ln1b   = (const float*)d_in[3];
    const float* ln2g   = (const float*)d_in[4];
    const float* ln2b   = (const float*)d_in[5];
    const float* Wqkv_v = (const float*)d_in[6];
    const float* bqkv_v = (const float*)d_in[7];
    const float* Wqkv_i = (const float*)d_in[8];
    const float* bqkv_i = (const float*)d_in[9];
    const float* Wo_v   = (const float*)d_in[10];
    const float* bo_v   = (const float*)d_in[11];
    const float* Wo_i   = (const float*)d_in[12];
    const float* bo_i   = (const float*)d_in[13];
    const float* blng   = (const float*)d_in[14];
    const float* blnb   = (const float*)d_in[15];
    const float* W1_v   = (const float*)d_in[16];
    const float* b1_v   = (const float*)d_in[17];
    const float* W2_v   = (const float*)d_in[18];
    const float* b2_v   = (const float*)d_in[19];
    const float* W1_i   = (const float*)d_in[20];
    const float* b1_i   = (const float*)d_in[21];
    const float* W2_i   = (const float*)d_in[22];
    const float* b2_i   = (const float*)d_in[23];
    const float* coef   = (const float*)d_in[24];
    float* out = (float*)d_out;

    __nv_bfloat16 *xln, *wqkv, *wo, *w1, *w2, *qkv, *Pb, *Ob, *attln, *hb;
    float *Sb, *attb;
    cudaGetSymbolAddress((void**)&xln,   g_xln);
    cudaGetSymbolAddress((void**)&wqkv,  g_wqkv);
    cudaGetSymbolAddress((void**)&wo,    g_wo);
    cudaGetSymbolAddress((void**)&w1,    g_w1);
    cudaGetSymbolAddress((void**)&w2,    g_w2);
    cudaGetSymbolAddress((void**)&qkv,   g_qkv);
    cudaGetSymbolAddress((void**)&Sb,    g_Smat);
    cudaGetSymbolAddress((void**)&Pb,    g_Pmat);
    cudaGetSymbolAddress((void**)&Ob,    g_Omat);
    cudaGetSymbolAddress((void**)&attb,  g_att);
    cudaGetSymbolAddress((void**)&attln, g_attln);
    cudaGetSymbolAddress((void**)&hb,    g_hid);

    cudaFuncSetAttribute(gemm_k<0, false>, cudaFuncAttributeMaxDynamicSharedMemorySize, SMEM_NN);
    cudaFuncSetAttribute(gemm_k<3, false>, cudaFuncAttributeMaxDynamicSharedMemorySize, SMEM_NN);
    cudaFuncSetAttribute(gemm_k<4, false>, cudaFuncAttributeMaxDynamicSharedMemorySize, SMEM_NN);
    cudaFuncSetAttribute(gemm_k<1, true>,  cudaFuncAttributeMaxDynamicSharedMemorySize, SMEM_NT);

    // weights -> bf16 (one launch, 8 regions)
    {
        CvtP cp{};
        cp.s[0] = Wqkv_v; cp.d[0] = wqkv;            cp.n[0] = 3145728L;
        cp.s[1] = Wqkv_i; cp.d[1] = wqkv + 3145728L; cp.n[1] = 3145728L;
        cp.s[2] = Wo_v;   cp.d[2] = wo;              cp.n[2] = 1048576L;
        cp.s[3] = Wo_i;   cp.d[3] = wo + 1048576L;   cp.n[3] = 1048576L;
        cp.s[4] = W1_v;   cp.d[4] = w1;              cp.n[4] = 4194304L;
        cp.s[5] = W1_i;   cp.d[5] = w1 + 4194304L;   cp.n[5] = 4194304L;
        cp.s[6] = W2_v;   cp.d[6] = w2;              cp.n[6] = 4194304L;
        cp.s[7] = W2_i;   cp.d[7] = w2 + 4194304L;   cp.n[7] = 4194304L;
        cvt8_k<<<dim3(4096, 8), 256>>>(cp);
    }

    // input LayerNorms (one launch)
    ln2_k<<<dim3(16384, 2), 256>>>(rgb, xln, ln1g, ln1b,
                                   irp, xln + 16777216L, ln2g, ln2b);

    // QKV projections: ONE launch, 6 instances (M=16384 N=1024 K=1024)
    {
        GPM p{};
        for (int s = 0; s < 2; s++)
            for (int t = 0; t < 3; t++) {
                int g = s*3 + t;
                p.A[g] = xln + (long)s * 16777216L;
                p.B[g] = wqkv + (long)g * 1048576L;
                p.C[g] = qkv + (long)g * 16777216L;
                p.bias[g] = (s == 0 ? bqkv_v : bqkv_i) + t * 1024;
            }
        p.lda = 1024; p.ldb = 1024; p.ldc = 1024;
        p.ZG = 1; p.Hh = 1; p.K = 1024; p.coeffs = coef;
        gemm_k<0, false><<<dim3(8, 128, 6), 256, SMEM_NN>>>(p);
    }

    // scores S = Q @ K^T * scale: ONE launch, 2 dirs x 512 (b,h)
    {
        GPM p{};
        p.A[0] = qkv + (1L*3 + 0) * 16777216L;  // q_ir
        p.B[0] = qkv + (0L*3 + 1) * 16777216L;  // k_vis
        p.C[0] = Sb;
        p.A[1] = qkv + (0L*3 + 0) * 16777216L;  // q_vis
        p.B[1] = qkv + (1L*3 + 1) * 16777216L;  // k_ir
        p.C[1] = Sb + 33554432L;
        p.lda = 1024; p.ldb = 1024; p.ldc = 256;
        p.sAb = 262144; p.sAh = 128; p.sBb = 262144; p.sBh = 128;
        p.sCb = 524288; p.sCh = 65536;
        p.ZG = 512; p.Hh = 8; p.K = 128;
        p.alpha = 0.08838834764831845f; p.coeffs = coef;
        gemm_k<1, true><<<dim3(2, 2, 1024), 256, SMEM_NT>>>(p);
    }

    softmax_k<<<32768, 256>>>(Sb, Pb);

    // O = P @ V: ONE launch, 2 dirs x 512
    {
        GPM p{};
        p.A[0] = Pb;              p.B[0] = qkv + (0L*3 + 2) * 16777216L;  p.C[0] = Ob;
        p.A[1] = Pb + 33554432L;  p.B[1] = qkv + (1L*3 + 2) * 16777216L;  p.C[1] = Ob + 16777216L;
        p.bias[0] = nullptr; p.bias[1] = nullptr;
        p.lda = 256;  p.ldb = 1024; p.ldc = 1024;
        p.sAb = 524288; p.sAh = 65536; p.sBb = 262144; p.sBh = 128;
        p.sCb = 262144; p.sCh = 128;
        p.ZG = 512; p.Hh = 8; p.K = 256; p.coeffs = coef;
        gemm_k<0, false><<<dim3(1, 2, 1024), 256, SMEM_NN>>>(p);
    }

    // output projection + residual: ONE launch, 2 instances
    {
        GPM p{};
        p.A[0] = Ob;              p.B[0] = wo;              p.C[0] = attb;
        p.bias[0] = bo_v; p.resid[0] = rgb;
        p.A[1] = Ob + 16777216L;  p.B[1] = wo + 1048576L;   p.C[1] = attb + 16777216L;
        p.bias[1] = bo_i; p.resid[1] = irp;
        p.lda = 1024; p.ldb = 1024; p.ldc = 1024; p.ldr = 1024;
        p.ZG = 1; p.Hh = 1; p.K = 1024; p.coeffs = coef; p.ci0base = 0;
        gemm_k<3, false><<<dim3(8, 128, 2), 256, SMEM_NN>>>(p);
    }

    // block LayerNorm (one launch, shared gamma/beta)
    ln2_k<<<dim3(16384, 2), 256>>>(attb, attln, blng, blnb,
                                   attb + 16777216L, attln + 16777216L, blng, blnb);

    // MLP layer 1 + exact GELU: ONE launch, 2 instances (N=4096 K=1024)
    {
        GPM p{};
        p.A[0] = attln;              p.B[0] = w1;             p.C[0] = hb;
        p.bias[0] = b1_v;
        p.A[1] = attln + 16777216L;  p.B[1] = w1 + 4194304L;  p.C[1] = hb + 67108864L;
        p.bias[1] = b1_i;
        p.lda = 1024; p.ldb = 4096; p.ldc = 4096;
        p.ZG = 1; p.Hh = 1; p.K = 1024; p.coeffs = coef;
        gemm_k<4, false><<<dim3(32, 128, 2), 256, SMEM_NN>>>(p);
    }

    // MLP layer 2 + final combine -> d_out: ONE launch, 2 instances (K=4096)
    {
        GPM p{};
        p.A[0] = hb;              p.B[0] = w2;             p.C[0] = out;
        p.bias[0] = b2_v; p.resid[0] = attb;
        p.A[1] = hb + 67108864L;  p.B[1] = w2 + 4194304L;  p.C[1] = out + 16777216L;
        p.bias[1] = b2_i; p.resid[1] = attb + 16777216L;
        p.lda = 4096; p.ldb = 1024; p.ldc = 1024; p.ldr = 1024;
        p.ZG = 1; p.Hh = 1; p.K = 4096; p.coeffs = coef; p.ci0base = 4;
        gemm_k<3, false><<<dim3(8, 128, 2), 256, SMEM_NN>>>(p);
    }
}

// round 14
// speedup vs baseline: 1.3712x; 1.3712x over previous
#include <cuda_runtime.h>
#include <cuda_bf16.h>
#include <mma.h>
#include <cstdint>

using namespace nvcuda;

// ---------------- device scratch (static; no allocations) ----------------
__device__ __nv_bfloat16 g_xln  [2L*16384*1024];
__device__ __nv_bfloat16 g_wqkv [2L*3*1024*1024];
__device__ __nv_bfloat16 g_wo   [2L*1024*1024];
__device__ __nv_bfloat16 g_w1   [2L*1024*4096];
__device__ __nv_bfloat16 g_w2   [2L*4096*1024];
__device__ __nv_bfloat16 g_qkv  [2L*3*16384*1024];
__device__ __nv_bfloat16 g_Omat [2L*16384*1024];
__device__ float         g_att  [2L*16384*1024];
__device__ __nv_bfloat16 g_attln[2L*16384*1024];
__device__ __nv_bfloat16 g_hid  [2L*16384*4096];

// ---------------- helpers ----------------
__device__ __forceinline__ uint32_t smem_u32(const void* p) {
    uint32_t a;
    asm("{ .reg .u64 t; cvta.to.shared.u64 t, %1; cvt.u32.u64 %0, t; }" : "=r"(a) : "l"(p));
    return a;
}
__device__ __forceinline__ void cpa16(uint32_t d, const void* s) {
    asm volatile("cp.async.cg.shared.global [%0], [%1], 16;" :: "r"(d), "l"(s));
}
#define CP_COMMIT() asm volatile("cp.async.commit_group;" ::: "memory")

// ---------------- fused convert (8 regions, one launch) ----------------
struct CvtP {
    const float* s[8];
    __nv_bfloat16* d[8];
    long n[8];
};
__global__ void cvt8_k(CvtP p) {
    int reg = blockIdx.y;
    long i = (long)blockIdx.x * 1024 + threadIdx.x;
    const float* s = p.s[reg];
    __nv_bfloat16* d = p.d[reg];
    long n = p.n[reg];
#pragma unroll
    for (int it = 0; it < 4; ++it) {
        long j = i + (long)it * 256;
        if (j < n) d[j] = __float2bfloat16(s[j]);
    }
}

// ---------------- fused dual LayerNorm ----------------
__global__ void ln2_k(const float* __restrict__ x0, __nv_bfloat16* __restrict__ y0,
                      const float* __restrict__ g0, const float* __restrict__ b0,
                      const float* __restrict__ x1, __nv_bfloat16* __restrict__ y1,
                      const float* __restrict__ g1, const float* __restrict__ b1) {
    const float* x = blockIdx.y ? x1 : x0;
    __nv_bfloat16* y = blockIdx.y ? y1 : y0;
    const float* gam = blockIdx.y ? g1 : g0;
    const float* bet = blockIdx.y ? b1 : b0;
    long row = blockIdx.x;
    const float* xr = x + row * 1024;
    int tid = threadIdx.x;
    float v[4]; float s = 0.f, s2 = 0.f;
#pragma unroll
    for (int i = 0; i < 4; i++) { float t = xr[tid + i*256]; v[i] = t; s += t; s2 += t*t; }
#pragma unroll
    for (int o = 16; o; o >>= 1) {
        s  += __shfl_xor_sync(0xffffffffu, s,  o);
        s2 += __shfl_xor_sync(0xffffffffu, s2, o);
    }
    __shared__ float sh[2][8];
    if ((tid & 31) == 0) { sh[0][tid>>5] = s; sh[1][tid>>5] = s2; }
    __syncthreads();
    float S = 0.f, S2 = 0.f;
#pragma unroll
    for (int w = 0; w < 8; w++) { S += sh[0][w]; S2 += sh[1][w]; }
    float m   = S  * (1.f/1024.f);
    float var = S2 * (1.f/1024.f) - m*m;
    float inv = rsqrtf(var + 1e-5f);
#pragma unroll
    for (int i = 0; i < 4; i++) {
        int c = tid + i*256;
        y[row*1024 + c] = __float2bfloat16((v[i]-m)*inv*gam[c] + bet[c]);
    }
}

// ---------------- fused attention: S=QK^T, softmax, O=PV, one CTA per (dir,b,h,qtile) ----------------
static const int FA_LDQ = 136;                    // elems (Q/K/V tiles)
static const int FA_LDS = 264;                    // elems (S/P)
static const int FA_Q_B   = 128 * FA_LDQ * 2;     // 34816
static const int FA_KV_B  = 256 * FA_LDQ * 2;     // 69632
static const int FA_S_B   = 128 * FA_LDS * 2;     // 67584
static const int FA_SCR_B = 8 * 16 * 20 * 4;      // 10240
static const int FA_SMEM  = FA_Q_B + FA_KV_B + FA_S_B + FA_SCR_B;  // 182272

__global__ void __launch_bounds__(256) fattn_k(const __nv_bfloat16* __restrict__ qkv,
                                               __nv_bfloat16* __restrict__ Ob) {
    extern __shared__ char sm[];
    __nv_bfloat16* Qs = (__nv_bfloat16*)sm;
    __nv_bfloat16* Ks = (__nv_bfloat16*)(sm + FA_Q_B);            // K, later V
    __nv_bfloat16* Ss = (__nv_bfloat16*)(sm + FA_Q_B + FA_KV_B);  // S / P
    float* scr = (float*)(sm + FA_Q_B + FA_KV_B + FA_S_B);

    const int tid = threadIdx.x, warp = tid >> 5, lane = tid & 31;
    const int ct  = blockIdx.x;
    const int dir = ct >> 10;
    const int rem = ct & 1023;
    const int b   = rem >> 4;
    const int h   = (rem >> 1) & 7;
    const int qt  = rem & 1;
    const int qs  = dir ? 0 : 1;   // dir0: q_ir/k_vis ; dir1: q_vis/k_ir
    const int ks  = dir ? 1 : 0;

    const __nv_bfloat16* Qp = qkv + ((long)(qs*3 + 0) << 24) + (long)b*262144 + h*128 + (long)qt*131072;
    const __nv_bfloat16* Kp = qkv + ((long)(ks*3 + 1) << 24) + (long)b*262144 + h*128;
    const __nv_bfloat16* Vp = qkv + ((long)(ks*3 + 2) << 24) + (long)b*262144 + h*128;
    __nv_bfloat16* Op = Ob + ((long)dir << 24) + (long)b*262144 + h*128 + (long)qt*131072;

    // ---- load Q (128x128) and K (256x128) ----
    for (int i = tid; i < 128*16; i += 256) {
        int r = i >> 4, c = i & 15;
        *(uint4*)&Qs[r*FA_LDQ + c*8] = *(const uint4*)(Qp + (long)r*1024 + c*8);
    }
    for (int i = tid; i < 256*16; i += 256) {
        int r = i >> 4, c = i & 15;
        *(uint4*)&Ks[r*FA_LDQ + c*8] = *(const uint4*)(Kp + (long)r*1024 + c*8);
    }
    __syncthreads();

    const int wm = warp >> 2, wn = warp & 3;   // 2x4 warp grid

    // ---- S = Q @ K^T (scaled -> bf16 smem) ----
    {
        wmma::fragment<wmma::accumulator, 16, 16, 16, float> sacc[4][4];
#pragma unroll
        for (int i = 0; i < 4; i++)
#pragma unroll
            for (int j = 0; j < 4; j++) wmma::fill_fragment(sacc[i][j], 0.f);

        for (int kk = 0; kk < 128; kk += 16) {
            wmma::fragment<wmma::matrix_a, 16, 16, 16, __nv_bfloat16, wmma::row_major> fa[4];
            wmma::fragment<wmma::matrix_b, 16, 16, 16, __nv_bfloat16, wmma::col_major> fb[4];
#pragma unroll
            for (int mi = 0; mi < 4; ++mi)
                wmma::load_matrix_sync(fa[mi], &Qs[(wm*64 + mi*16)*FA_LDQ + kk], FA_LDQ);
#pragma unroll
            for (int ni = 0; ni < 4; ++ni)
                wmma::load_matrix_sync(fb[ni], &Ks[(wn*64 + ni*16)*FA_LDQ + kk], FA_LDQ);
#pragma unroll
            for (int mi = 0; mi < 4; ++mi)
#pragma unroll
                for (int ni = 0; ni < 4; ++ni)
                    wmma::mma_sync(sacc[mi][ni], fa[mi], fb[ni], sacc[mi][ni]);
        }

        const float scale = 0.08838834764831845f;
        float* sp = scr + warp * 16 * 20;
#pragma unroll
        for (int mi = 0; mi < 4; ++mi)
#pragma unroll
            for (int ni = 0; ni < 4; ++ni) {
                wmma::store_matrix_sync(sp, sacc[mi][ni], 20, wmma::mem_row_major);
                __syncwarp();
#pragma unroll
                for (int e = 0; e < 8; ++e) {
                    int i = e*32 + lane;
                    int r = i >> 4, c = i & 15;
                    int gr = wm*64 + mi*16 + r, gc = wn*64 + ni*16 + c;
                    Ss[gr*FA_LDS + gc] = __float2bfloat16(sp[r*20 + c] * scale);
                }
                __syncwarp();
            }
    }
    __syncthreads();

    // ---- softmax over 256 cols, 16 rows per warp ----
    for (int rr = 0; rr < 16; ++rr) {
        int row = warp*16 + rr;
        float v[8]; float mx = -1e30f;
#pragma unroll
        for (int e = 0; e < 8; ++e) {
            v[e] = __bfloat162float(Ss[row*FA_LDS + e*32 + lane]);
            mx = fmaxf(mx, v[e]);
        }
#pragma unroll
        for (int o = 16; o; o >>= 1) mx = fmaxf(mx, __shfl_xor_sync(0xffffffffu, mx, o));
        float s = 0.f;
#pragma unroll
        for (int e = 0; e < 8; ++e) { v[e] = __expf(v[e] - mx); s += v[e]; }
#pragma unroll
        for (int o = 16; o; o >>= 1) s += __shfl_xor_sync(0xffffffffu, s, o);
        float inv = 1.f / s;
#pragma unroll
        for (int e = 0; e < 8; ++e)
            Ss[row*FA_LDS + e*32 + lane] = __float2bfloat16(v[e] * inv);
    }
    __syncthreads();

    // ---- load V (256x128) over K's smem ----
    for (int i = tid; i < 256*16; i += 256) {
        int r = i >> 4, c = i & 15;
        *(uint4*)&Ks[r*FA_LDQ + c*8] = *(const uint4*)(Vp + (long)r*1024 + c*8);
    }
    __syncthreads();

    // ---- O = P @ V ---- warp tile 64(m) x 32(n)
    {
        wmma::fragment<wmma::accumulator, 16, 16, 16, float> oacc[4][2];
#pragma unroll
        for (int i = 0; i < 4; i++)
#pragma unroll
            for (int j = 0; j < 2; j++) wmma::fill_fragment(oacc[i][j], 0.f);

        for (int kk = 0; kk < 256; kk += 16) {
            wmma::fragment<wmma::matrix_a, 16, 16, 16, __nv_bfloat16, wmma::row_major> fa[4];
            wmma::fragment<wmma::matrix_b, 16, 16, 16, __nv_bfloat16, wmma::row_major> fb[2];
#pragma unroll
            for (int mi = 0; mi < 4; ++mi)
                wmma::load_matrix_sync(fa[mi], &Ss[(wm*64 + mi*16)*FA_LDS + kk], FA_LDS);
#pragma unroll
            for (int ni = 0; ni < 2; ++ni)
                wmma::load_matrix_sync(fb[ni], &Ks[kk*FA_LDQ + wn*32 + ni*16], FA_LDQ);
#pragma unroll
            for (int mi = 0; mi < 4; ++mi)
#pragma unroll
                for (int ni = 0; ni < 2; ++ni)
                    wmma::mma_sync(oacc[mi][ni], fa[mi], fb[ni], oacc[mi][ni]);
        }

        float* sp = scr + warp * 16 * 20;
#pragma unroll
        for (int mi = 0; mi < 4; ++mi)
#pragma unroll
            for (int ni = 0; ni < 2; ++ni) {
                wmma::store_matrix_sync(sp, oacc[mi][ni], 20, wmma::mem_row_major);
                __syncwarp();
#pragma unroll
                for (int e = 0; e < 8; ++e) {
                    int i = e*32 + lane;
                    int r = i >> 4, c = i & 15;
                    int gr = wm*64 + mi*16 + r, gc = wn*32 + ni*16 + c;
                    Op[(long)gr*1024 + gc] = __float2bfloat16(sp[r*20 + c]);
                }
                __syncwarp();
            }
    }
}

// ---------------- GEMM params ----------------
struct GP {
    const __nv_bfloat16* A;
    const __nv_bfloat16* B;
    long lda, ldb, ldc;
    int  K;
    void* C;
    const float* bias;
    const float* resid; long ldr;
    const float* coeffs; int ci0, ci1;
};

// ---------------- pipelined wmma GEMM: 256 thr, BK=64, reg double-buffered (R10 proven) ----------------
// EPI: 0 = bf16 store + bias, 3 = fp32 c_res*resid + c_out*(acc+bias), 4 = bf16 gelu(acc+bias)
static const int BM = 128, BN = 128, BK = 64;
static const int STG = 3;
static const int LDA_S  = BK + 8;        // 72 elems = 144 B
static const int LDB_NN = BN + 8;        // 136 elems = 272 B
static const int EPLD   = 20;
static const int A_STG_B   = BM * LDA_S * 2;      // 18432 B
static const int B_STG_NN  = BK * LDB_NN * 2;     // 17408 B
static const int SMEM_NN   = STG * (A_STG_B + B_STG_NN);  // 107520

template <int EPI>
__global__ void __launch_bounds__(256) gemm_k(GP p) {
    extern __shared__ char dsm[];
    const int tid  = threadIdx.x;
    const int warp = tid >> 5, lane = tid & 31;
    const int wm = warp >> 2, wn = warp & 3;   // 2x4 warp grid, 64x32 warp tile

    const int row0 = blockIdx.y * BM;
    const int col0 = blockIdx.x * BN;
    const long lda = p.lda, ldb = p.ldb;
    const __nv_bfloat16* Ab = p.A;
    const __nv_bfloat16* Bb = p.B;

    const uint32_t asb = smem_u32(dsm);
    const uint32_t bsb = asb + STG * A_STG_B;
    __nv_bfloat16* As = (__nv_bfloat16*)dsm;
    __nv_bfloat16* Bs = (__nv_bfloat16*)(dsm + STG * A_STG_B);

    auto load_stage = [&](int slot, int k0) {
        uint32_t ab = asb + slot * A_STG_B;
#pragma unroll
        for (int it = 0; it < 4; ++it) {
            int id = tid + it*256;
            int r = id >> 3, c = id & 7;
            cpa16(ab + r*144 + c*16, Ab + (long)(row0 + r)*lda + k0 + c*8);
        }
        uint32_t bbp = bsb + slot * B_STG_NN;
#pragma unroll
        for (int it = 0; it < 4; ++it) {
            int id = tid + it*256;
            int r = id >> 4, c = id & 15;
            cpa16(bbp + r*272 + c*16, Bb + (long)(k0 + r)*ldb + col0 + c*8);
        }
    };

    wmma::fragment<wmma::accumulator, 16, 16, 16, float> acc[4][2];
#pragma unroll
    for (int i = 0; i < 4; i++)
#pragma unroll
        for (int j = 0; j < 2; j++) wmma::fill_fragment(acc[i][j], 0.f);

    wmma::fragment<wmma::matrix_a, 16, 16, 16, __nv_bfloat16, wmma::row_major> fa[2][4];
    wmma::fragment<wmma::matrix_b, 16, 16, 16, __nv_bfloat16, wmma::row_major> fbr[2][2];

    const int kiters = p.K >> 6;

#pragma unroll
    for (int s = 0; s < STG-1; ++s) {
        if (s < kiters) load_stage(s, s * BK);
        CP_COMMIT();
    }

    for (int k = 0; k < kiters; ++k) {
        asm volatile("cp.async.wait_group %0;" :: "n"(STG-2));
        __syncthreads();
        int pf = k + STG - 1;
        if (pf < kiters) load_stage(pf % STG, pf * BK);
        CP_COMMIT();

        int slot = k % STG;
        __nv_bfloat16* Asl = As + slot * (BM * LDA_S);
        __nv_bfloat16* BslNN = Bs + slot * (BK * LDB_NN);

#pragma unroll
        for (int mi = 0; mi < 4; ++mi)
            wmma::load_matrix_sync(fa[0][mi], &Asl[(wm*64 + mi*16)*LDA_S + 0], LDA_S);
#pragma unroll
        for (int ni = 0; ni < 2; ++ni)
            wmma::load_matrix_sync(fbr[0][ni], &BslNN[0*LDB_NN + wn*32 + ni*16], LDB_NN);

#pragma unroll
        for (int j = 0; j < 4; ++j) {
            int cur = j & 1, nxt = cur ^ 1;
            if (j < 3) {
                int kk = (j + 1) * 16;
#pragma unroll
                for (int mi = 0; mi < 4; ++mi)
                    wmma::load_matrix_sync(fa[nxt][mi], &Asl[(wm*64 + mi*16)*LDA_S + kk], LDA_S);
#pragma unroll
                for (int ni = 0; ni < 2; ++ni)
                    wmma::load_matrix_sync(fbr[nxt][ni], &BslNN[kk*LDB_NN + wn*32 + ni*16], LDB_NN);
            }
#pragma unroll
            for (int mi = 0; mi < 4; ++mi)
#pragma unroll
                for (int ni = 0; ni < 2; ++ni)
                    wmma::mma_sync(acc[mi][ni], fa[cur][mi], fbr[cur][ni], acc[mi][ni]);
        }
    }
    __syncthreads();   // protect smem reuse in epilogue

    float c_res = 0.f, c_out = 0.f;
    if (EPI == 3) { c_res = p.coeffs[p.ci0]; c_out = p.coeffs[p.ci1]; }
    float* ep = (float*)dsm;
    float* eptr = &ep[warp * 16 * EPLD];
#pragma unroll
    for (int mi = 0; mi < 4; ++mi) {
#pragma unroll
        for (int ni = 0; ni < 2; ++ni) {
            wmma::store_matrix_sync(eptr, acc[mi][ni], EPLD, wmma::mem_row_major);
            __syncwarp();
            int r0 = row0 + wm*64 + mi*16;
            int c0 = col0 + wn*32 + ni*16;
#pragma unroll
            for (int e = 0; e < 8; ++e) {
                int i = e*32 + lane;
                int r = i >> 4, c = i & 15;
                float v = eptr[r*EPLD + c];
                long gr = r0 + r, gc = c0 + c;
                long cidx = gr*p.ldc + gc;
                if (EPI == 0) {
                    v += p.bias[gc];
                    ((__nv_bfloat16*)p.C)[cidx] = __float2bfloat16(v);
                } else if (EPI == 3) {
                    v += p.bias[gc];
                    ((float*)p.C)[cidx] = c_res * p.resid[gr*p.ldr + gc] + c_out * v;
                } else if (EPI == 4) {
                    v += p.bias[gc];
                    float gl = 0.5f * v * (1.f + erff(v * 0.70710678118654752f));
                    ((__nv_bfloat16*)p.C)[cidx] = __float2bfloat16(gl);
                }
            }
            __syncwarp();
        }
    }
}

// ---------------- host orchestration ----------------
extern "C" void kernel_launch(void* const* d_in, const int* in_sizes, int n_in,
                              void* d_out, int out_size) {
    (void)in_sizes; (void)n_in; (void)out_size;
    const float* rgb    = (const float*)d_in[0];
    const float* irp    = (const float*)d_in[1];
    const float* ln1g   = (const float*)d_in[2];
    const float* ln1b   = (const float*)d_in[3];
    const float* ln2g   = (const float*)d_in[4];
    const float* ln2b   = (const float*)d_in[5];
    const float* Wqkv_v = (const float*)d_in[6];
    const float* bqkv_v = (const float*)d_in[7];
    const float* Wqkv_i = (const float*)d_in[8];
    const float* bqkv_i = (const float*)d_in[9];
    const float* Wo_v   = (const float*)d_in[10];
    const float* bo_v   = (const float*)d_in[11];
    const float* Wo_i   = (const float*)d_in[12];
    const float* bo_i   = (const float*)d_in[13];
    const float* blng   = (const float*)d_in[14];
    const float* blnb   = (const float*)d_in[15];
    const float* W1_v   = (const float*)d_in[16];
    const float* b1_v   = (const float*)d_in[17];
    const float* W2_v   = (const float*)d_in[18];
    const float* b2_v   = (const float*)d_in[19];
    const float* W1_i   = (const float*)d_in[20];
    const float* b1_i   = (const float*)d_in[21];
    const float* W2_i   = (const float*)d_in[22];
    const float* b2_i   = (const float*)d_in[23];
    const float* coef   = (const float*)d_in[24];
    float* out = (float*)d_out;

    __nv_bfloat16 *xln, *wqkv, *wo, *w1, *w2, *qkv, *Ob, *attln, *hb;
    float *attb;
    cudaGetSymbolAddress((void**)&xln,   g_xln);
    cudaGetSymbolAddress((void**)&wqkv,  g_wqkv);
    cudaGetSymbolAddress((void**)&wo,    g_wo);
    cudaGetSymbolAddress((void**)&w1,    g_w1);
    cudaGetSymbolAddress((void**)&w2,    g_w2);
    cudaGetSymbolAddress((void**)&qkv,   g_qkv);
    cudaGetSymbolAddress((void**)&Ob,    g_Omat);
    cudaGetSymbolAddress((void**)&attb,  g_att);
    cudaGetSymbolAddress((void**)&attln, g_attln);
    cudaGetSymbolAddress((void**)&hb,    g_hid);

    cudaFuncSetAttribute(gemm_k<0>, cudaFuncAttributeMaxDynamicSharedMemorySize, SMEM_NN);
    cudaFuncSetAttribute(gemm_k<3>, cudaFuncAttributeMaxDynamicSharedMemorySize, SMEM_NN);
    cudaFuncSetAttribute(gemm_k<4>, cudaFuncAttributeMaxDynamicSharedMemorySize, SMEM_NN);
    cudaFuncSetAttribute(fattn_k,   cudaFuncAttributeMaxDynamicSharedMemorySize, FA_SMEM);

    // weights -> bf16 (one launch, 8 regions)
    {
        CvtP cp{};
        cp.s[0] = Wqkv_v; cp.d[0] = wqkv;            cp.n[0] = 3145728L;
        cp.s[1] = Wqkv_i; cp.d[1] = wqkv + 3145728L; cp.n[1] = 3145728L;
        cp.s[2] = Wo_v;   cp.d[2] = wo;              cp.n[2] = 1048576L;
        cp.s[3] = Wo_i;   cp.d[3] = wo + 1048576L;   cp.n[3] = 1048576L;
        cp.s[4] = W1_v;   cp.d[4] = w1;              cp.n[4] = 4194304L;
        cp.s[5] = W1_i;   cp.d[5] = w1 + 4194304L;   cp.n[5] = 4194304L;
        cp.s[6] = W2_v;   cp.d[6] = w2;              cp.n[6] = 4194304L;
        cp.s[7] = W2_i;   cp.d[7] = w2 + 4194304L;   cp.n[7] = 4194304L;
        cvt8_k<<<dim3(4096, 8), 256>>>(cp);
    }

    // input LayerNorms (one launch)
    ln2_k<<<dim3(16384, 2), 256>>>(rgb, xln, ln1g, ln1b,
                                   irp, xln + 16777216L, ln2g, ln2b);

    // QKV projections (6 separate launches — R10 proven config)
    for (int s = 0; s < 2; s++) {
        for (int t = 0; t < 3; t++) {
            GP p{};
            p.A = xln + (long)s * 16777216L;                 p.lda = 1024;
            p.B = wqkv + ((long)s*3 + t) * 1048576L;         p.ldb = 1024;
            p.C = qkv + ((long)s*3 + t) * 16777216L;         p.ldc = 1024;
            p.bias = (s == 0 ? bqkv_v : bqkv_i) + t * 1024;
            p.K = 1024; p.coeffs = coef;
            gemm_k<0><<<dim3(8, 128), 256, SMEM_NN>>>(p);
        }
    }

    // fused attention: scores + softmax + PV in one launch
    fattn_k<<<2048, 256, FA_SMEM>>>(qkv, Ob);

    // output projection + residual
    for (int dir = 0; dir < 2; ++dir) {
        GP p{};
        p.A = Ob + (long)dir * 16777216L;   p.lda = 1024;
        p.B = wo + (long)dir * 1048576L;    p.ldb = 1024;
        p.C = attb + (long)dir * 16777216L; p.ldc = 1024;
        p.bias = (dir == 0) ? bo_v : bo_i;
        p.resid = (dir == 0) ? rgb : irp;   p.ldr = 1024;
        p.coeffs = coef; p.ci0 = 2*dir; p.ci1 = 2*dir + 1;
        p.K = 1024;
        gemm_k<3><<<dim3(8, 128), 256, SMEM_NN>>>(p);
    }

    // block LayerNorm (one launch, shared gamma/beta)
    ln2_k<<<dim3(16384, 2), 256>>>(attb, attln, blng, blnb,
                                   attb + 16777216L, attln + 16777216L, blng, blnb);

    // MLP layer 1 + exact GELU (M=16384 N=4096 K=1024)
    for (int s = 0; s < 2; s++) {
        GP p{};
        p.A = attln + (long)s * 16777216L;  p.lda = 1024;
        p.B = w1 + (long)s * 4194304L;      p.ldb = 4096;
        p.C = hb + (long)s * 67108864L;     p.ldc = 4096;
        p.bias = (s == 0) ? b1_v : b1_i;
        p.K = 1024; p.coeffs = coef;
        gemm_k<4><<<dim3(32, 128), 256, SMEM_NN>>>(p);
    }

    // MLP layer 2 + final combine -> d_out (M=16384 N=1024 K=4096)
    for (int s = 0; s < 2; s++) {
        GP p{};
        p.A = hb + (long)s * 67108864L;     p.lda = 4096;
        p.B = w2 + (long)s * 4194304L;      p.ldb = 1024;
        p.C = out + (long)s * 16777216L;    p.ldc = 1024;
        p.bias = (s == 0) ? b2_v : b2_i;
        p.resid = attb + (long)s * 16777216L; p.ldr = 1024;
        p.coeffs = coef; p.ci0 = 4 + 2*s; p.ci1 = 5 + 2*s;
        p.K = 4096;
        gemm_k<3><<<dim3(8, 128), 256, SMEM_NN>>>(p);
    }
}

// round 15
// speedup vs baseline: 1.5054x; 1.0979x over previous
#include <cuda_runtime.h>
#include <cuda_bf16.h>
#include <mma.h>
#include <cstdint>

using namespace nvcuda;

// ---------------- device scratch (static; no allocations) ----------------
__device__ __nv_bfloat16 g_xln  [2L*16384*1024];
__device__ __nv_bfloat16 g_wqkv [2L*3*1024*1024];
__device__ __nv_bfloat16 g_wo   [2L*1024*1024];
__device__ __nv_bfloat16 g_w1   [2L*1024*4096];
__device__ __nv_bfloat16 g_w2   [2L*4096*1024];
__device__ __nv_bfloat16 g_qkv  [2L*3*16384*1024];
__device__ float         g_Smat [1024L*256*256];
__device__ __nv_bfloat16 g_Pmat [1024L*256*256];
__device__ __nv_bfloat16 g_Omat [2L*16384*1024];
__device__ float         g_att  [2L*16384*1024];
__device__ __nv_bfloat16 g_attln[2L*16384*1024];
__device__ __nv_bfloat16 g_hid  [2L*16384*4096];

// ---------------- helpers ----------------
__device__ __forceinline__ uint32_t smem_u32(const void* p) {
    uint32_t a;
    asm("{ .reg .u64 t; cvta.to.shared.u64 t, %1; cvt.u32.u64 %0, t; }" : "=r"(a) : "l"(p));
    return a;
}
__device__ __forceinline__ void cpa16(uint32_t d, const void* s) {
    asm volatile("cp.async.cg.shared.global [%0], [%1], 16;" :: "r"(d), "l"(s));
}
#define CP_COMMIT() asm volatile("cp.async.commit_group;" ::: "memory")

// ---------------- fused convert (8 regions, one launch) ----------------
struct CvtP {
    const float* s[8];
    __nv_bfloat16* d[8];
    long n[8];
};
__global__ void cvt8_k(CvtP p) {
    int reg = blockIdx.y;
    long i = (long)blockIdx.x * 1024 + threadIdx.x;
    const float* s = p.s[reg];
    __nv_bfloat16* d = p.d[reg];
    long n = p.n[reg];
#pragma unroll
    for (int it = 0; it < 4; ++it) {
        long j = i + (long)it * 256;
        if (j < n) d[j] = __float2bfloat16(s[j]);
    }
}

// ---------------- fused dual LayerNorm ----------------
__global__ void ln2_k(const float* __restrict__ x0, __nv_bfloat16* __restrict__ y0,
                      const float* __restrict__ g0, const float* __restrict__ b0,
                      const float* __restrict__ x1, __nv_bfloat16* __restrict__ y1,
                      const float* __restrict__ g1, const float* __restrict__ b1) {
    const float* x = blockIdx.y ? x1 : x0;
    __nv_bfloat16* y = blockIdx.y ? y1 : y0;
    const float* gam = blockIdx.y ? g1 : g0;
    const float* bet = blockIdx.y ? b1 : b0;
    long row = blockIdx.x;
    const float* xr = x + row * 1024;
    int tid = threadIdx.x;
    float v[4]; float s = 0.f, s2 = 0.f;
#pragma unroll
    for (int i = 0; i < 4; i++) { float t = xr[tid + i*256]; v[i] = t; s += t; s2 += t*t; }
#pragma unroll
    for (int o = 16; o; o >>= 1) {
        s  += __shfl_xor_sync(0xffffffffu, s,  o);
        s2 += __shfl_xor_sync(0xffffffffu, s2, o);
    }
    __shared__ float sh[2][8];
    if ((tid & 31) == 0) { sh[0][tid>>5] = s; sh[1][tid>>5] = s2; }
    __syncthreads();
    float S = 0.f, S2 = 0.f;
#pragma unroll
    for (int w = 0; w < 8; w++) { S += sh[0][w]; S2 += sh[1][w]; }
    float m   = S  * (1.f/1024.f);
    float var = S2 * (1.f/1024.f) - m*m;
    float inv = rsqrtf(var + 1e-5f);
#pragma unroll
    for (int i = 0; i < 4; i++) {
        int c = tid + i*256;
        y[row*1024 + c] = __float2bfloat16((v[i]-m)*inv*gam[c] + bet[c]);
    }
}

__global__ void softmax_k(const float* __restrict__ S, __nv_bfloat16* __restrict__ P) {
    long row = (long)blockIdx.x * 8 + (threadIdx.x >> 5);
    int lane = threadIdx.x & 31;
    const float* sr = S + row * 256;
    float v[8]; float m = -1e30f;
#pragma unroll
    for (int e = 0; e < 8; e++) { v[e] = sr[e*32 + lane]; m = fmaxf(m, v[e]); }
#pragma unroll
    for (int o = 16; o; o >>= 1) m = fmaxf(m, __shfl_xor_sync(0xffffffffu, m, o));
    float s = 0.f;
#pragma unroll
    for (int e = 0; e < 8; e++) { v[e] = __expf(v[e] - m); s += v[e]; }
#pragma unroll
    for (int o = 16; o; o >>= 1) s += __shfl_xor_sync(0xffffffffu, s, o);
    float inv = 1.f / s;
#pragma unroll
    for (int e = 0; e < 8; e++)
        P[row*256 + e*32 + lane] = __float2bfloat16(v[e] * inv);
}

// ---------------- GEMM params ----------------
struct GP {
    const __nv_bfloat16* A;
    const __nv_bfloat16* B;
    long lda, ldb, ldc;
    long sAb, sAh, sBb, sBh, sCb, sCh;
    int  Hh;
    int  K;
    void* C;
    const float* bias;
    const float* resid; long ldr;
    const float* coeffs; int ci0, ci1;
    float alpha;
};

// ---------------- pipelined wmma GEMM: 256 thr, BK=64, reg double-buffered ----------------
// EPI: 0 = bf16 store (+opt bias), 1 = fp32 store * alpha,
//      3 = fp32 store: c_res*resid + c_out*(acc+bias), 4 = bf16 gelu(acc+bias)
static const int BM = 128, BN = 128, BK = 64;
static const int STG = 3;
static const int LDA_S  = BK + 8;        // 72 elems = 144 B
static const int LDB_NN = BN + 8;        // 136 elems = 272 B
static const int LDB_NT = BK + 8;        // 72
static const int EPW    = 132;           // full-tile epilogue staging stride (fp32)
static const int A_STG_B   = BM * LDA_S * 2;      // 18432 B
static const int B_STG_NN  = BK * LDB_NN * 2;     // 17408 B
static const int B_STG_NT  = BN * LDB_NT * 2;     // 18432 B
static const int SMEM_NN   = STG * (A_STG_B + B_STG_NN);  // 107520 (>= 128*132*4 = 67584)
static const int SMEM_NT   = STG * (A_STG_B + B_STG_NT);  // 110592

template <int EPI, bool TB>
__global__ void __launch_bounds__(256) gemm_k(GP p) {
    extern __shared__ char dsm[];
    const int tid  = threadIdx.x;
    const int warp = tid >> 5;
    const int wm = warp >> 2, wn = warp & 3;   // 2x4 warp grid, 64x32 warp tile

    const int z  = blockIdx.z;
    const int bb = z / p.Hh, hh = z - bb * p.Hh;
    const __nv_bfloat16* Ab = p.A + (long)bb * p.sAb + (long)hh * p.sAh;
    const __nv_bfloat16* Bb = p.B + (long)bb * p.sBb + (long)hh * p.sBh;
    const long coff = (long)bb * p.sCb + (long)hh * p.sCh;

    const int row0 = blockIdx.y * BM;
    const int col0 = blockIdx.x * BN;
    const long lda = p.lda, ldb = p.ldb;

    const uint32_t asb = smem_u32(dsm);
    const uint32_t bsb = asb + STG * A_STG_B;
    __nv_bfloat16* As = (__nv_bfloat16*)dsm;
    __nv_bfloat16* Bs = (__nv_bfloat16*)(dsm + STG * A_STG_B);

    auto load_stage = [&](int slot, int k0) {
        uint32_t ab = asb + slot * A_STG_B;
#pragma unroll
        for (int it = 0; it < 4; ++it) {
            int id = tid + it*256;
            int r = id >> 3, c = id & 7;
            cpa16(ab + r*144 + c*16, Ab + (long)(row0 + r)*lda + k0 + c*8);
        }
        if (!TB) {
            uint32_t bbp = bsb + slot * B_STG_NN;
#pragma unroll
            for (int it = 0; it < 4; ++it) {
                int id = tid + it*256;
                int r = id >> 4, c = id & 15;
                cpa16(bbp + r*272 + c*16, Bb + (long)(k0 + r)*ldb + col0 + c*8);
            }
        } else {
            uint32_t bbp = bsb + slot * B_STG_NT;
#pragma unroll
            for (int it = 0; it < 4; ++it) {
                int id = tid + it*256;
                int r = id >> 3, c = id & 7;
                cpa16(bbp + r*144 + c*16, Bb + (long)(col0 + r)*ldb + k0 + c*8);
            }
        }
    };

    wmma::fragment<wmma::accumulator, 16, 16, 16, float> acc[4][2];
#pragma unroll
    for (int i = 0; i < 4; i++)
#pragma unroll
        for (int j = 0; j < 2; j++) wmma::fill_fragment(acc[i][j], 0.f);

    wmma::fragment<wmma::matrix_a, 16, 16, 16, __nv_bfloat16, wmma::row_major> fa[2][4];
    wmma::fragment<wmma::matrix_b, 16, 16, 16, __nv_bfloat16, wmma::row_major> fbr[2][2];
    wmma::fragment<wmma::matrix_b, 16, 16, 16, __nv_bfloat16, wmma::col_major> fbc[2][2];

    const int kiters = p.K >> 6;

#pragma unroll
    for (int s = 0; s < STG-1; ++s) {
        if (s < kiters) load_stage(s, s * BK);
        CP_COMMIT();
    }

    for (int k = 0; k < kiters; ++k) {
        asm volatile("cp.async.wait_group %0;" :: "n"(STG-2));
        __syncthreads();
        int pf = k + STG - 1;
        if (pf < kiters) load_stage(pf % STG, pf * BK);
        CP_COMMIT();

        int slot = k % STG;
        __nv_bfloat16* Asl = As + slot * (BM * LDA_S);
        __nv_bfloat16* BslNN = Bs + slot * (BK * LDB_NN);
        __nv_bfloat16* BslNT = Bs + slot * (BN * LDB_NT);

#pragma unroll
        for (int mi = 0; mi < 4; ++mi)
            wmma::load_matrix_sync(fa[0][mi], &Asl[(wm*64 + mi*16)*LDA_S + 0], LDA_S);
        if (!TB) {
#pragma unroll
            for (int ni = 0; ni < 2; ++ni)
                wmma::load_matrix_sync(fbr[0][ni], &BslNN[0*LDB_NN + wn*32 + ni*16], LDB_NN);
        } else {
#pragma unroll
            for (int ni = 0; ni < 2; ++ni)
                wmma::load_matrix_sync(fbc[0][ni], &BslNT[(wn*32 + ni*16)*LDB_NT + 0], LDB_NT);
        }

#pragma unroll
        for (int j = 0; j < 4; ++j) {
            int cur = j & 1, nxt = cur ^ 1;
            if (j < 3) {
                int kk = (j + 1) * 16;
#pragma unroll
                for (int mi = 0; mi < 4; ++mi)
                    wmma::load_matrix_sync(fa[nxt][mi], &Asl[(wm*64 + mi*16)*LDA_S + kk], LDA_S);
                if (!TB) {
#pragma unroll
                    for (int ni = 0; ni < 2; ++ni)
                        wmma::load_matrix_sync(fbr[nxt][ni], &BslNN[kk*LDB_NN + wn*32 + ni*16], LDB_NN);
                } else {
#pragma unroll
                    for (int ni = 0; ni < 2; ++ni)
                        wmma::load_matrix_sync(fbc[nxt][ni], &BslNT[(wn*32 + ni*16)*LDB_NT + kk], LDB_NT);
                }
            }
            if (!TB) {
#pragma unroll
                for (int mi = 0; mi < 4; ++mi)
#pragma unroll
                    for (int ni = 0; ni < 2; ++ni)
                        wmma::mma_sync(acc[mi][ni], fa[cur][mi], fbr[cur][ni], acc[mi][ni]);
            } else {
#pragma unroll
                for (int mi = 0; mi < 4; ++mi)
#pragma unroll
                    for (int ni = 0; ni < 2; ++ni)
                        wmma::mma_sync(acc[mi][ni], fa[cur][mi], fbc[cur][ni], acc[mi][ni]);
            }
        }
    }
    __syncthreads();   // mainloop smem is dead; reuse dsm for epilogue staging

    // ---------------- one-shot full-tile epilogue ----------------
    float* ep = (float*)dsm;   // 128 x EPW fp32 tile
#pragma unroll
    for (int mi = 0; mi < 4; ++mi)
#pragma unroll
        for (int ni = 0; ni < 2; ++ni)
            wmma::store_matrix_sync(&ep[(wm*64 + mi*16)*EPW + wn*32 + ni*16],
                                    acc[mi][ni], EPW, wmma::mem_row_major);
    __syncthreads();

    float c_res = 0.f, c_out = 0.f;
    if (EPI == 3) { c_res = p.coeffs[p.ci0]; c_out = p.coeffs[p.ci1]; }
    const int tr  = tid >> 5;    // 0..7
    const int tc4 = tid & 31;    // 0..31 (float4 column index)
    const int gc  = col0 + tc4 * 4;
#pragma unroll
    for (int it = 0; it < 16; ++it) {
        int r = tr + it * 8;
        long gr = row0 + r;
        float4 v4 = *(float4*)&ep[r * EPW + tc4 * 4];
        long cidx = coff + gr * p.ldc + gc;
        if (EPI == 0) {
            if (p.bias) {
                float4 b4 = *(const float4*)&p.bias[gc];
                v4.x += b4.x; v4.y += b4.y; v4.z += b4.z; v4.w += b4.w;
            }
            __nv_bfloat162 h0 = __floats2bfloat162_rn(v4.x, v4.y);
            __nv_bfloat162 h1 = __floats2bfloat162_rn(v4.z, v4.w);
            uint2 u;
            u.x = *(uint32_t*)&h0; u.y = *(uint32_t*)&h1;
            *(uint2*)&((__nv_bfloat16*)p.C)[cidx] = u;
        } else if (EPI == 1) {
            v4.x *= p.alpha; v4.y *= p.alpha; v4.z *= p.alpha; v4.w *= p.alpha;
            *(float4*)&((float*)p.C)[cidx] = v4;
        } else if (EPI == 3) {
            float4 b4 = *(const float4*)&p.bias[gc];
            float4 r4 = *(const float4*)&p.resid[gr * p.ldr + gc];
            float4 o4;
            o4.x = c_res * r4.x + c_out * (v4.x + b4.x);
            o4.y = c_res * r4.y + c_out * (v4.y + b4.y);
            o4.z = c_res * r4.z + c_out * (v4.z + b4.z);
            o4.w = c_res * r4.w + c_out * (v4.w + b4.w);
            *(float4*)&((float*)p.C)[cidx] = o4;
        } else if (EPI == 4) {
            float4 b4 = *(const float4*)&p.bias[gc];
            v4.x += b4.x; v4.y += b4.y; v4.z += b4.z; v4.w += b4.w;
            const float is2 = 0.70710678118654752f;
            float g0 = 0.5f * v4.x * (1.f + erff(v4.x * is2));
            float g1 = 0.5f * v4.y * (1.f + erff(v4.y * is2));
            float g2 = 0.5f * v4.z * (1.f + erff(v4.z * is2));
            float g3 = 0.5f * v4.w * (1.f + erff(v4.w * is2));
            __nv_bfloat162 h0 = __floats2bfloat162_rn(g0, g1);
            __nv_bfloat162 h1 = __floats2bfloat162_rn(g2, g3);
            uint2 u;
            u.x = *(uint32_t*)&h0; u.y = *(uint32_t*)&h1;
            *(uint2*)&((__nv_bfloat16*)p.C)[cidx] = u;
        }
    }
}

// ---------------- host orchestration ----------------
extern "C" void kernel_launch(void* const* d_in, const int* in_sizes, int n_in,
                              void* d_out, int out_size) {
    (void)in_sizes; (void)n_in; (void)out_size;
    const float* rgb    = (const float*)d_in[0];
    const float* irp    = (const float*)d_in[1];
    const float* ln1g   = (const float*)d_in[2];
    const float* ln1b   = (const float*)d_in[3];
    const float* ln2g   = (const float*)d_in[4];
    const float* ln2b   = (const float*)d_in[5];
    const float* Wqkv_v = (const float*)d_in[6];
    const float* bqkv_v = (const float*)d_in[7];
    const float* Wqkv_i = (const float*)d_in[8];
    const float* bqkv_i = (const float*)d_in[9];
    const float* Wo_v   = (const float*)d_in[10];
    const float* bo_v   = (const float*)d_in[11];
    const float* Wo_i   = (const float*)d_in[12];
    const float* bo_i   = (const float*)d_in[13];
    const float* blng   = (const float*)d_in[14];
    const float* blnb   = (const float*)d_in[15];
    const float* W1_v   = (const float*)d_in[16];
    const float* b1_v   = (const float*)d_in[17];
    const float* W2_v   = (const float*)d_in[18];
    const float* b2_v   = (const float*)d_in[19];
    const float* W1_i   = (const float*)d_in[20];
    const float* b1_i   = (const float*)d_in[21];
    const float* W2_i   = (const float*)d_in[22];
    const float* b2_i   = (const float*)d_in[23];
    const float* coef   = (const float*)d_in[24];
    float* out = (float*)d_out;

    __nv_bfloat16 *xln, *wqkv, *wo, *w1, *w2, *qkv, *Pb, *Ob, *attln, *hb;
    float *Sb, *attb;
    cudaGetSymbolAddress((void**)&xln,   g_xln);
    cudaGetSymbolAddress((void**)&wqkv,  g_wqkv);
    cudaGetSymbolAddress((void**)&wo,    g_wo);
    cudaGetSymbolAddress((void**)&w1,    g_w1);
    cudaGetSymbolAddress((void**)&w2,    g_w2);
    cudaGetSymbolAddress((void**)&qkv,   g_qkv);
    cudaGetSymbolAddress((void**)&Sb,    g_Smat);
    cudaGetSymbolAddress((void**)&Pb,    g_Pmat);
    cudaGetSymbolAddress((void**)&Ob,    g_Omat);
    cudaGetSymbolAddress((void**)&attb,  g_att);
    cudaGetSymbolAddress((void**)&attln, g_attln);
    cudaGetSymbolAddress((void**)&hb,    g_hid);

    cudaFuncSetAttribute(gemm_k<0, false>, cudaFuncAttributeMaxDynamicSharedMemorySize, SMEM_NN);
    cudaFuncSetAttribute(gemm_k<3, false>, cudaFuncAttributeMaxDynamicSharedMemorySize, SMEM_NN);
    cudaFuncSetAttribute(gemm_k<4, false>, cudaFuncAttributeMaxDynamicSharedMemorySize, SMEM_NN);
    cudaFuncSetAttribute(gemm_k<1, true>,  cudaFuncAttributeMaxDynamicSharedMemorySize, SMEM_NT);

    // weights -> bf16 (one launch, 8 regions)
    {
        CvtP cp{};
        cp.s[0] = Wqkv_v; cp.d[0] = wqkv;            cp.n[0] = 3145728L;
        cp.s[1] = Wqkv_i; cp.d[1] = wqkv + 3145728L; cp.n[1] = 3145728L;
        cp.s[2] = Wo_v;   cp.d[2] = wo;              cp.n[2] = 1048576L;
        cp.s[3] = Wo_i;   cp.d[3] = wo + 1048576L;   cp.n[3] = 1048576L;
        cp.s[4] = W1_v;   cp.d[4] = w1;              cp.n[4] = 4194304L;
        cp.s[5] = W1_i;   cp.d[5] = w1 + 4194304L;   cp.n[5] = 4194304L;
        cp.s[6] = W2_v;   cp.d[6] = w2;              cp.n[6] = 4194304L;
        cp.s[7] = W2_i;   cp.d[7] = w2 + 4194304L;   cp.n[7] = 4194304L;
        cvt8_k<<<dim3(4096, 8), 256>>>(cp);
    }

    // input LayerNorms (one launch)
    ln2_k<<<dim3(16384, 2), 256>>>(rgb, xln, ln1g, ln1b,
                                   irp, xln + 16777216L, ln2g, ln2b);

    // QKV projections (6 GEMMs, M=16384 N=1024 K=1024)
    for (int s = 0; s < 2; s++) {
        for (int t = 0; t < 3; t++) {
            GP p{};
            p.A = xln + (long)s * 16777216L;                 p.lda = 1024;
            p.B = wqkv + ((long)s*3 + t) * 1048576L;         p.ldb = 1024;
            p.C = qkv + ((long)s*3 + t) * 16777216L;         p.ldc = 1024;
            p.bias = (s == 0 ? bqkv_v : bqkv_i) + t * 1024;
            p.Hh = 1; p.K = 1024; p.coeffs = coef;
            gemm_k<0, false><<<dim3(8, 128, 1), 256, SMEM_NN>>>(p);
        }
    }

    // scores S = Q @ K^T * scale  (batched over b,h)
    for (int dir = 0; dir < 2; ++dir) {
        int qs = (dir == 0) ? 1 : 0;
        int ks = (dir == 0) ? 0 : 1;
        GP p{};
        p.A = qkv + ((long)qs*3 + 0) * 16777216L;  p.lda = 1024; p.sAb = 262144; p.sAh = 128;
        p.B = qkv + ((long)ks*3 + 1) * 16777216L;  p.ldb = 1024; p.sBb = 262144; p.sBh = 128;
        p.C = Sb + (long)dir * 33554432L;          p.ldc = 256;  p.sCb = 524288; p.sCh = 65536;
        p.Hh = 8; p.K = 128; p.alpha = 0.08838834764831845f; p.coeffs = coef;
        gemm_k<1, true><<<dim3(2, 2, 512), 256, SMEM_NT>>>(p);
    }

    softmax_k<<<32768, 256>>>(Sb, Pb);

    // O = P @ V (batched), merged layout
    for (int dir = 0; dir < 2; ++dir) {
        int ks = (dir == 0) ? 0 : 1;
        GP p{};
        p.A = Pb + (long)dir * 33554432L;          p.lda = 256;  p.sAb = 524288; p.sAh = 65536;
        p.B = qkv + ((long)ks*3 + 2) * 16777216L;  p.ldb = 1024; p.sBb = 262144; p.sBh = 128;
        p.C = Ob + (long)dir * 16777216L;          p.ldc = 1024; p.sCb = 262144; p.sCh = 128;
        p.bias = nullptr; p.Hh = 8; p.K = 256; p.coeffs = coef;
        gemm_k<0, false><<<dim3(1, 2, 512), 256, SMEM_NN>>>(p);
    }

    // output projection + residual
    for (int dir = 0; dir < 2; ++dir) {
        GP p{};
        p.A = Ob + (long)dir * 16777216L;   p.lda = 1024;
        p.B = wo + (long)dir * 1048576L;    p.ldb = 1024;
        p.C = attb + (long)dir * 16777216L; p.ldc = 1024;
        p.bias = (dir == 0) ? bo_v : bo_i;
        p.resid = (dir == 0) ? rgb : irp;   p.ldr = 1024;
        p.coeffs = coef; p.ci0 = 2*dir; p.ci1 = 2*dir + 1;
        p.Hh = 1; p.K = 1024;
        gemm_k<3, false><<<dim3(8, 128, 1), 256, SMEM_NN>>>(p);
    }

    // block LayerNorm (one launch, shared gamma/beta)
    ln2_k<<<dim3(16384, 2), 256>>>(attb, attln, blng, blnb,
                                   attb + 16777216L, attln + 16777216L, blng, blnb);

    // MLP layer 1 + exact GELU (M=16384 N=4096 K=1024)
    for (int s = 0; s < 2; s++) {
        GP p{};
        p.A = attln + (long)s * 16777216L;  p.lda = 1024;
        p.B = w1 + (long)s * 4194304L;      p.ldb = 4096;
        p.C = hb + (long)s * 67108864L;     p.ldc = 4096;
        p.bias = (s == 0) ? b1_v : b1_i;
        p.Hh = 1; p.K = 1024; p.coeffs = coef;
        gemm_k<4, false><<<dim3(32, 128, 1), 256, SMEM_NN>>>(p);
    }

    // MLP layer 2 + final combine -> d_out (M=16384 N=1024 K=4096)
    for (int s = 0; s < 2; s++) {
        GP p{};
        p.A = hb + (long)s * 67108864L;     p.lda = 4096;
        p.B = w2 + (long)s * 4194304L;      p.ldb = 1024;
        p.C = out + (long)s * 16777216L;    p.ldc = 1024;
        p.bias = (s == 0) ? b2_v : b2_i;
        p.resid = attb + (long)s * 16777216L; p.ldr = 1024;
        p.coeffs = coef; p.ci0 = 4 + 2*s; p.ci1 = 5 + 2*s;
        p.Hh = 1; p.K = 4096;
        gemm_k<3, false><<<dim3(8, 128, 1), 256, SMEM_NN>>>(p);
    }
}

// round 16
// speedup vs baseline: 1.5442x; 1.0258x over previous
#include <cuda_runtime.h>
#include <cuda_bf16.h>
#include <mma.h>
#include <cstdint>

using namespace nvcuda;

// ---------------- device scratch (static; no allocations) ----------------
__device__ __nv_bfloat16 g_xln  [2L*16384*1024];
__device__ __nv_bfloat16 g_wqkv [2L*1024*3072];     // interleaved [stream][K=1024][3N=3072]
__device__ __nv_bfloat16 g_wo   [2L*1024*1024];
__device__ __nv_bfloat16 g_w1   [2L*1024*4096];
__device__ __nv_bfloat16 g_w2   [2L*4096*1024];
__device__ __nv_bfloat16 g_qkv  [2L*16384*3072];    // [stream][row][Q|K|V]
__device__ float         g_Smat [1024L*256*256];
__device__ __nv_bfloat16 g_Pmat [1024L*256*256];
__device__ __nv_bfloat16 g_Omat [2L*16384*1024];
__device__ float         g_att  [2L*16384*1024];
__device__ __nv_bfloat16 g_attln[2L*16384*1024];
__device__ __nv_bfloat16 g_hid  [2L*16384*4096];

// ---------------- helpers ----------------
__device__ __forceinline__ uint32_t smem_u32(const void* p) {
    uint32_t a;
    asm("{ .reg .u64 t; cvta.to.shared.u64 t, %1; cvt.u32.u64 %0, t; }" : "=r"(a) : "l"(p));
    return a;
}
__device__ __forceinline__ void cpa16(uint32_t d, const void* s) {
    asm volatile("cp.async.cg.shared.global [%0], [%1], 16;" :: "r"(d), "l"(s));
}
#define CP_COMMIT() asm volatile("cp.async.commit_group;" ::: "memory")

// ---------------- fused convert (6 plain regions) ----------------
struct CvtP {
    const float* s[6];
    __nv_bfloat16* d[6];
    long n[6];
};
__global__ void cvt6_k(CvtP p) {
    int reg = blockIdx.y;
    long i = (long)blockIdx.x * 1024 + threadIdx.x;
    const float* s = p.s[reg];
    __nv_bfloat16* d = p.d[reg];
    long n = p.n[reg];
#pragma unroll
    for (int it = 0; it < 4; ++it) {
        long j = i + (long)it * 256;
        if (j < n) d[j] = __float2bfloat16(s[j]);
    }
}

// qkv weights: [3][1024][1024] per stream -> interleaved [1024][3*1024]
__global__ void cvtqkv_k(const float* __restrict__ wv, const float* __restrict__ wi,
                         __nv_bfloat16* __restrict__ d) {
    const float* s = blockIdx.y ? wi : wv;
    __nv_bfloat16* ds = d + (long)blockIdx.y * 3145728L;
    long idx = (long)blockIdx.x * 256 + threadIdx.x;
    if (idx < 3145728L) {
        int t   = (int)(idx >> 20);
        int rem = (int)(idx & 1048575);
        int kk  = rem >> 10;
        int n   = rem & 1023;
        ds[(long)kk*3072 + t*1024 + n] = __float2bfloat16(s[idx]);
    }
}

// ---------------- fused dual LayerNorm ----------------
__global__ void ln2_k(const float* __restrict__ x0, __nv_bfloat16* __restrict__ y0,
                      const float* __restrict__ g0, const float* __restrict__ b0,
                      const float* __restrict__ x1, __nv_bfloat16* __restrict__ y1,
                      const float* __restrict__ g1, const float* __restrict__ b1) {
    const float* x = blockIdx.y ? x1 : x0;
    __nv_bfloat16* y = blockIdx.y ? y1 : y0;
    const float* gam = blockIdx.y ? g1 : g0;
    const float* bet = blockIdx.y ? b1 : b0;
    long row = blockIdx.x;
    const float* xr = x + row * 1024;
    int tid = threadIdx.x;
    float v[4]; float s = 0.f, s2 = 0.f;
#pragma unroll
    for (int i = 0; i < 4; i++) { float t = xr[tid + i*256]; v[i] = t; s += t; s2 += t*t; }
#pragma unroll
    for (int o = 16; o; o >>= 1) {
        s  += __shfl_xor_sync(0xffffffffu, s,  o);
        s2 += __shfl_xor_sync(0xffffffffu, s2, o);
    }
    __shared__ float sh[2][8];
    if ((tid & 31) == 0) { sh[0][tid>>5] = s; sh[1][tid>>5] = s2; }
    __syncthreads();
    float S = 0.f, S2 = 0.f;
#pragma unroll
    for (int w = 0; w < 8; w++) { S += sh[0][w]; S2 += sh[1][w]; }
    float m   = S  * (1.f/1024.f);
    float var = S2 * (1.f/1024.f) - m*m;
    float inv = rsqrtf(var + 1e-5f);
#pragma unroll
    for (int i = 0; i < 4; i++) {
        int c = tid + i*256;
        y[row*1024 + c] = __float2bfloat16((v[i]-m)*inv*gam[c] + bet[c]);
    }
}

__global__ void softmax_k(const float* __restrict__ S, __nv_bfloat16* __restrict__ P) {
    long row = (long)blockIdx.x * 8 + (threadIdx.x >> 5);
    int lane = threadIdx.x & 31;
    const float* sr = S + row * 256;
    float v[8]; float m = -1e30f;
#pragma unroll
    for (int e = 0; e < 8; e++) { v[e] = sr[e*32 + lane]; m = fmaxf(m, v[e]); }
#pragma unroll
    for (int o = 16; o; o >>= 1) m = fmaxf(m, __shfl_xor_sync(0xffffffffu, m, o));
    float s = 0.f;
#pragma unroll
    for (int e = 0; e < 8; e++) { v[e] = __expf(v[e] - m); s += v[e]; }
#pragma unroll
    for (int o = 16; o; o >>= 1) s += __shfl_xor_sync(0xffffffffu, s, o);
    float inv = 1.f / s;
#pragma unroll
    for (int e = 0; e < 8; e++)
        P[row*256 + e*32 + lane] = __float2bfloat16(v[e] * inv);
}

// ---------------- GEMM params ----------------
struct GP {
    const __nv_bfloat16* A;
    const __nv_bfloat16* B;
    const __nv_bfloat16* B2;      // second-half weights (M-merged launches)
    void* C;
    const float* bias;
    const float* bias2;
    const float* resid;
    const float* resid2;
    long lda, ldb, ldc, ldr;
    long sAb, sAh, sBb, sBh, sCb, sCh;
    int  Hh;
    int  K;
    int  Msplit;                  // 0 = no M split
    const float* coeffs; int ci0, ci1, ci0b, ci1b;
    float alpha;
};

// ---------------- pipelined wmma GEMM: 256 thr, BK=64, reg double-buffered ----------------
// EPI: 0 = bf16 store (+opt bias), 1 = fp32 store * alpha,
//      3 = fp32 store: c_res*resid + c_out*(acc+bias), 4 = bf16 gelu(acc+bias)
static const int BM = 128, BN = 128, BK = 64;
static const int STG = 3;
static const int LDA_S  = BK + 8;        // 72 elems = 144 B
static const int LDB_NN = BN + 8;        // 136 elems = 272 B
static const int LDB_NT = BK + 8;        // 72
static const int EPW    = 132;           // full-tile epilogue staging stride (fp32)
static const int A_STG_B   = BM * LDA_S * 2;      // 18432 B
static const int B_STG_NN  = BK * LDB_NN * 2;     // 17408 B
static const int B_STG_NT  = BN * LDB_NT * 2;     // 18432 B
static const int SMEM_NN   = STG * (A_STG_B + B_STG_NN);  // 107520
static const int SMEM_NT   = STG * (A_STG_B + B_STG_NT);  // 110592

template <int EPI, bool TB>
__global__ void __launch_bounds__(256) gemm_k(GP p) {
    extern __shared__ char dsm[];
    const int tid  = threadIdx.x;
    const int warp = tid >> 5;
    const int wm = warp >> 2, wn = warp & 3;   // 2x4 warp grid, 64x32 warp tile

    const int z  = blockIdx.z;
    const int bb = z / p.Hh, hh = z - bb * p.Hh;
    const int row0 = blockIdx.y * BM;
    const int col0 = blockIdx.x * BN;

    // instance selection for M-merged launches (uniform branch)
    const __nv_bfloat16* Bsel = p.B;
    const float* bias  = p.bias;
    const float* resid = p.resid;
    int ci0 = p.ci0, ci1 = p.ci1;
    if (p.Msplit && row0 >= p.Msplit) {
        Bsel = p.B2;
        bias = p.bias2;
        if (p.resid2) resid = p.resid2 - (long)p.Msplit * p.ldr;
        ci0 = p.ci0b; ci1 = p.ci1b;
    }

    const __nv_bfloat16* Ab = p.A + (long)bb * p.sAb + (long)hh * p.sAh;
    const __nv_bfloat16* Bb = Bsel + (long)bb * p.sBb + (long)hh * p.sBh;
    const long coff = (long)bb * p.sCb + (long)hh * p.sCh;
    const long lda = p.lda, ldb = p.ldb;

    const uint32_t asb = smem_u32(dsm);
    const uint32_t bsb = asb + STG * A_STG_B;
    __nv_bfloat16* As = (__nv_bfloat16*)dsm;
    __nv_bfloat16* Bs = (__nv_bfloat16*)(dsm + STG * A_STG_B);

    auto load_stage = [&](int slot, int k0) {
        uint32_t ab = asb + slot * A_STG_B;
#pragma unroll
        for (int it = 0; it < 4; ++it) {
            int id = tid + it*256;
            int r = id >> 3, c = id & 7;
            cpa16(ab + r*144 + c*16, Ab + (long)(row0 + r)*lda + k0 + c*8);
        }
        if (!TB) {
            uint32_t bbp = bsb + slot * B_STG_NN;
#pragma unroll
            for (int it = 0; it < 4; ++it) {
                int id = tid + it*256;
                int r = id >> 4, c = id & 15;
                cpa16(bbp + r*272 + c*16, Bb + (long)(k0 + r)*ldb + col0 + c*8);
            }
        } else {
            uint32_t bbp = bsb + slot * B_STG_NT;
#pragma unroll
            for (int it = 0; it < 4; ++it) {
                int id = tid + it*256;
                int r = id >> 3, c = id & 7;
                cpa16(bbp + r*144 + c*16, Bb + (long)(col0 + r)*ldb + k0 + c*8);
            }
        }
    };

    wmma::fragment<wmma::accumulator, 16, 16, 16, float> acc[4][2];
#pragma unroll
    for (int i = 0; i < 4; i++)
#pragma unroll
        for (int j = 0; j < 2; j++) wmma::fill_fragment(acc[i][j], 0.f);

    wmma::fragment<wmma::matrix_a, 16, 16, 16, __nv_bfloat16, wmma::row_major> fa[2][4];
    wmma::fragment<wmma::matrix_b, 16, 16, 16, __nv_bfloat16, wmma::row_major> fbr[2][2];
    wmma::fragment<wmma::matrix_b, 16, 16, 16, __nv_bfloat16, wmma::col_major> fbc[2][2];

    const int kiters = p.K >> 6;

#pragma unroll
    for (int s = 0; s < STG-1; ++s) {
        if (s < kiters) load_stage(s, s * BK);
        CP_COMMIT();
    }

    for (int k = 0; k < kiters; ++k) {
        asm volatile("cp.async.wait_group %0;" :: "n"(STG-2));
        __syncthreads();
        int pf = k + STG - 1;
        if (pf < kiters) load_stage(pf % STG, pf * BK);
        CP_COMMIT();

        int slot = k % STG;
        __nv_bfloat16* Asl = As + slot * (BM * LDA_S);
        __nv_bfloat16* BslNN = Bs + slot * (BK * LDB_NN);
        __nv_bfloat16* BslNT = Bs + slot * (BN * LDB_NT);

#pragma unroll
        for (int mi = 0; mi < 4; ++mi)
            wmma::load_matrix_sync(fa[0][mi], &Asl[(wm*64 + mi*16)*LDA_S + 0], LDA_S);
        if (!TB) {
#pragma unroll
            for (int ni = 0; ni < 2; ++ni)
                wmma::load_matrix_sync(fbr[0][ni], &BslNN[0*LDB_NN + wn*32 + ni*16], LDB_NN);
        } else {
#pragma unroll
            for (int ni = 0; ni < 2; ++ni)
                wmma::load_matrix_sync(fbc[0][ni], &BslNT[(wn*32 + ni*16)*LDB_NT + 0], LDB_NT);
        }

#pragma unroll
        for (int j = 0; j < 4; ++j) {
            int cur = j & 1, nxt = cur ^ 1;
            if (j < 3) {
                int kk = (j + 1) * 16;
#pragma unroll
                for (int mi = 0; mi < 4; ++mi)
                    wmma::load_matrix_sync(fa[nxt][mi], &Asl[(wm*64 + mi*16)*LDA_S + kk], LDA_S);
                if (!TB) {
#pragma unroll
                    for (int ni = 0; ni < 2; ++ni)
                        wmma::load_matrix_sync(fbr[nxt][ni], &BslNN[kk*LDB_NN + wn*32 + ni*16], LDB_NN);
                } else {
#pragma unroll
                    for (int ni = 0; ni < 2; ++ni)
                        wmma::load_matrix_sync(fbc[nxt][ni], &BslNT[(wn*32 + ni*16)*LDB_NT + kk], LDB_NT);
                }
            }
            if (!TB) {
#pragma unroll
                for (int mi = 0; mi < 4; ++mi)
#pragma unroll
                    for (int ni = 0; ni < 2; ++ni)
                        wmma::mma_sync(acc[mi][ni], fa[cur][mi], fbr[cur][ni], acc[mi][ni]);
            } else {
#pragma unroll
                for (int mi = 0; mi < 4; ++mi)
#pragma unroll
                    for (int ni = 0; ni < 2; ++ni)
                        wmma::mma_sync(acc[mi][ni], fa[cur][mi], fbc[cur][ni], acc[mi][ni]);
            }
        }
    }
    __syncthreads();   // mainloop smem is dead; reuse dsm for epilogue staging

    // ---------------- one-shot full-tile epilogue ----------------
    float* ep = (float*)dsm;   // 128 x EPW fp32 tile
#pragma unroll
    for (int mi = 0; mi < 4; ++mi)
#pragma unroll
        for (int ni = 0; ni < 2; ++ni)
            wmma::store_matrix_sync(&ep[(wm*64 + mi*16)*EPW + wn*32 + ni*16],
                                    acc[mi][ni], EPW, wmma::mem_row_major);
    __syncthreads();

    float c_res = 0.f, c_out = 0.f;
    if (EPI == 3) { c_res = p.coeffs[ci0]; c_out = p.coeffs[ci1]; }
    const int tr  = tid >> 5;    // 0..7
    const int tc4 = tid & 31;    // 0..31 (float4 column index)
    const int gc  = col0 + tc4 * 4;
#pragma unroll
    for (int it = 0; it < 16; ++it) {
        int r = tr + it * 8;
        long gr = row0 + r;
        float4 v4 = *(float4*)&ep[r * EPW + tc4 * 4];
        long cidx = coff + gr * p.ldc + gc;
        if (EPI == 0) {
            if (bias) {
                float4 b4 = *(const float4*)&bias[gc];
                v4.x += b4.x; v4.y += b4.y; v4.z += b4.z; v4.w += b4.w;
            }
            __nv_bfloat162 h0 = __floats2bfloat162_rn(v4.x, v4.y);
            __nv_bfloat162 h1 = __floats2bfloat162_rn(v4.z, v4.w);
            uint2 u;
            u.x = *(uint32_t*)&h0; u.y = *(uint32_t*)&h1;
            *(uint2*)&((__nv_bfloat16*)p.C)[cidx] = u;
        } else if (EPI == 1) {
            v4.x *= p.alpha; v4.y *= p.alpha; v4.z *= p.alpha; v4.w *= p.alpha;
            *(float4*)&((float*)p.C)[cidx] = v4;
        } else if (EPI == 3) {
            float4 b4 = *(const float4*)&bias[gc];
            float4 r4 = *(const float4*)&resid[gr * p.ldr + gc];
            float4 o4;
            o4.x = c_res * r4.x + c_out * (v4.x + b4.x);
            o4.y = c_res * r4.y + c_out * (v4.y + b4.y);
            o4.z = c_res * r4.z + c_out * (v4.z + b4.z);
            o4.w = c_res * r4.w + c_out * (v4.w + b4.w);
            *(float4*)&((float*)p.C)[cidx] = o4;
        } else if (EPI == 4) {
            float4 b4 = *(const float4*)&bias[gc];
            v4.x += b4.x; v4.y += b4.y; v4.z += b4.z; v4.w += b4.w;
            const float is2 = 0.70710678118654752f;
            float g0 = 0.5f * v4.x * (1.f + erff(v4.x * is2));
            float g1 = 0.5f * v4.y * (1.f + erff(v4.y * is2));
            float g2 = 0.5f * v4.z * (1.f + erff(v4.z * is2));
            float g3 = 0.5f * v4.w * (1.f + erff(v4.w * is2));
            __nv_bfloat162 h0 = __floats2bfloat162_rn(g0, g1);
            __nv_bfloat162 h1 = __floats2bfloat162_rn(g2, g3);
            uint2 u;
            u.x = *(uint32_t*)&h0; u.y = *(uint32_t*)&h1;
            *(uint2*)&((__nv_bfloat16*)p.C)[cidx] = u;
        }
    }
}

// ---------------- host orchestration ----------------
extern "C" void kernel_launch(void* const* d_in, const int* in_sizes, int n_in,
                              void* d_out, int out_size) {
    (void)in_sizes; (void)n_in; (void)out_size;
    const float* rgb    = (const float*)d_in[0];
    const float* irp    = (const float*)d_in[1];
    const float* ln1g   = (const float*)d_in[2];
    const float* ln1b   = (const float*)d_in[3];
    const float* ln2g   = (const float*)d_in[4];
    const float* ln2b   = (const float*)d_in[5];
    const float* Wqkv_v = (const float*)d_in[6];
    const float* bqkv_v = (const float*)d_in[7];
    const float* Wqkv_i = (const float*)d_in[8];
    const float* bqkv_i = (const float*)d_in[9];
    const float* Wo_v   = (const float*)d_in[10];
    const float* bo_v   = (const float*)d_in[11];
    const float* Wo_i   = (const float*)d_in[12];
    const float* bo_i   = (const float*)d_in[13];
    const float* blng   = (const float*)d_in[14];
    const float* blnb   = (const float*)d_in[15];
    const float* W1_v   = (const float*)d_in[16];
    const float* b1_v   = (const float*)d_in[17];
    const float* W2_v   = (const float*)d_in[18];
    const float* b2_v   = (const float*)d_in[19];
    const float* W1_i   = (const float*)d_in[20];
    const float* b1_i   = (const float*)d_in[21];
    const float* W2_i   = (const float*)d_in[22];
    const float* b2_i   = (const float*)d_in[23];
    const float* coef   = (const float*)d_in[24];
    float* out = (float*)d_out;

    __nv_bfloat16 *xln, *wqkv, *wo, *w1, *w2, *qkv, *Pb, *Ob, *attln, *hb;
    float *Sb, *attb;
    cudaGetSymbolAddress((void**)&xln,   g_xln);
    cudaGetSymbolAddress((void**)&wqkv,  g_wqkv);
    cudaGetSymbolAddress((void**)&wo,    g_wo);
    cudaGetSymbolAddress((void**)&w1,    g_w1);
    cudaGetSymbolAddress((void**)&w2,    g_w2);
    cudaGetSymbolAddress((void**)&qkv,   g_qkv);
    cudaGetSymbolAddress((void**)&Sb,    g_Smat);
    cudaGetSymbolAddress((void**)&Pb,    g_Pmat);
    cudaGetSymbolAddress((void**)&Ob,    g_Omat);
    cudaGetSymbolAddress((void**)&attb,  g_att);
    cudaGetSymbolAddress((void**)&attln, g_attln);
    cudaGetSymbolAddress((void**)&hb,    g_hid);

    cudaFuncSetAttribute(gemm_k<0, false>, cudaFuncAttributeMaxDynamicSharedMemorySize, SMEM_NN);
    cudaFuncSetAttribute(gemm_k<3, false>, cudaFuncAttributeMaxDynamicSharedMemorySize, SMEM_NN);
    cudaFuncSetAttribute(gemm_k<4, false>, cudaFuncAttributeMaxDynamicSharedMemorySize, SMEM_NN);
    cudaFuncSetAttribute(gemm_k<1, true>,  cudaFuncAttributeMaxDynamicSharedMemorySize, SMEM_NT);

    const long QS = 16384L * 3072;   // qkv stream stride

    // weights -> bf16: qkv interleaved + 6 plain regions
    cvtqkv_k<<<dim3(12288, 2), 256>>>(Wqkv_v, Wqkv_i, wqkv);
    {
        CvtP cp{};
        cp.s[0] = Wo_v; cp.d[0] = wo;            cp.n[0] = 1048576L;
        cp.s[1] = Wo_i; cp.d[1] = wo + 1048576L; cp.n[1] = 1048576L;
        cp.s[2] = W1_v; cp.d[2] = w1;            cp.n[2] = 4194304L;
        cp.s[3] = W1_i; cp.d[3] = w1 + 4194304L; cp.n[3] = 4194304L;
        cp.s[4] = W2_v; cp.d[4] = w2;            cp.n[4] = 4194304L;
        cp.s[5] = W2_i; cp.d[5] = w2 + 4194304L; cp.n[5] = 4194304L;
        cvt6_k<<<dim3(4096, 6), 256>>>(cp);
    }

    // input LayerNorms (one launch)
    ln2_k<<<dim3(16384, 2), 256>>>(rgb, xln, ln1g, ln1b,
                                   irp, xln + 16777216L, ln2g, ln2b);

    // QKV: ONE launch, M=32768, N=3072, K=1024
    {
        GP p{};
        p.A = xln;                 p.lda = 1024;
        p.B = wqkv;                p.B2 = wqkv + 3145728L;  p.ldb = 3072;
        p.C = qkv;                 p.ldc = 3072;
        p.bias = bqkv_v;           p.bias2 = bqkv_i;
        p.Msplit = 16384;
        p.Hh = 1; p.K = 1024; p.coeffs = coef;
        gemm_k<0, false><<<dim3(24, 256, 1), 256, SMEM_NN>>>(p);
    }

    // scores S = Q @ K^T * scale  (batched over b,h; Q/K at col offsets 0/1024)
    for (int dir = 0; dir < 2; ++dir) {
        int qs = (dir == 0) ? 1 : 0;
        int ks = (dir == 0) ? 0 : 1;
        GP p{};
        p.A = qkv + (long)qs * QS;           p.lda = 3072; p.sAb = 786432; p.sAh = 128;
        p.B = qkv + (long)ks * QS + 1024;    p.ldb = 3072; p.sBb = 786432; p.sBh = 128;
        p.C = Sb + (long)dir * 33554432L;    p.ldc = 256;  p.sCb = 524288; p.sCh = 65536;
        p.Hh = 8; p.K = 128; p.alpha = 0.08838834764831845f; p.coeffs = coef;
        gemm_k<1, true><<<dim3(2, 2, 512), 256, SMEM_NT>>>(p);
    }

    softmax_k<<<32768, 256>>>(Sb, Pb);

    // O = P @ V (batched; V at col offset 2048)
    for (int dir = 0; dir < 2; ++dir) {
        int ks = (dir == 0) ? 0 : 1;
        GP p{};
        p.A = Pb + (long)dir * 33554432L;   p.lda = 256;  p.sAb = 524288; p.sAh = 65536;
        p.B = qkv + (long)ks * QS + 2048;   p.ldb = 3072; p.sBb = 786432; p.sBh = 128;
        p.C = Ob + (long)dir * 16777216L;   p.ldc = 1024; p.sCb = 262144; p.sCh = 128;
        p.bias = nullptr; p.Hh = 8; p.K = 256; p.coeffs = coef;
        gemm_k<0, false><<<dim3(1, 2, 512), 256, SMEM_NN>>>(p);
    }

    // output projection + residual: ONE launch, M=32768
    {
        GP p{};
        p.A = Ob;                 p.lda = 1024;
        p.B = wo;                 p.B2 = wo + 1048576L;   p.ldb = 1024;
        p.C = attb;               p.ldc = 1024;
        p.bias = bo_v;            p.bias2 = bo_i;
        p.resid = rgb;            p.resid2 = irp;         p.ldr = 1024;
        p.Msplit = 16384;
        p.coeffs = coef; p.ci0 = 0; p.ci1 = 1; p.ci0b = 2; p.ci1b = 3;
        p.Hh = 1; p.K = 1024;
        gemm_k<3, false><<<dim3(8, 256, 1), 256, SMEM_NN>>>(p);
    }

    // block LayerNorm (one launch, shared gamma/beta)
    ln2_k<<<dim3(16384, 2), 256>>>(attb, attln, blng, blnb,
                                   attb + 16777216L, attln + 16777216L, blng, blnb);

    // MLP layer 1 + exact GELU: ONE launch, M=32768, N=4096, K=1024
    {
        GP p{};
        p.A = attln;              p.lda = 1024;
        p.B = w1;                 p.B2 = w1 + 4194304L;   p.ldb = 4096;
        p.C = hb;                 p.ldc = 4096;
        p.bias = b1_v;            p.bias2 = b1_i;
        p.Msplit = 16384;
        p.Hh = 1; p.K = 1024; p.coeffs = coef;
        gemm_k<4, false><<<dim3(32, 256, 1), 256, SMEM_NN>>>(p);
    }

    // MLP layer 2 + final combine -> d_out: ONE launch, M=32768, K=4096
    {
        GP p{};
        p.A = hb;                 p.lda = 4096;
        p.B = w2;                 p.B2 = w2 + 4194304L;   p.ldb = 1024;
        p.C = out;                p.ldc = 1024;
        p.bias = b2_v;            p.bias2 = b2_i;
        p.resid = attb;           p.resid2 = nullptr;     p.ldr = 1024;
        p.Msplit = 16384;
        p.coeffs = coef; p.ci0 = 4; p.ci1 = 5; p.ci0b = 6; p.ci1b = 7;
        p.Hh = 1; p.K = 4096;
        gemm_k<3, false><<<dim3(8, 256, 1), 256, SMEM_NN>>>(p);
    }
}

// round 17
// speedup vs baseline: 1.5480x; 1.0024x over previous
#include <cuda_runtime.h>
#include <cuda_bf16.h>
#include <mma.h>
#include <cstdint>

using namespace nvcuda;

// ---------------- device scratch (static; no allocations) ----------------
__device__ __nv_bfloat16 g_xln  [2L*16384*1024];
__device__ __nv_bfloat16 g_wqkv [2L*1024*3072];     // interleaved [stream][K=1024][3N=3072]
__device__ __nv_bfloat16 g_wo   [2L*1024*1024];
__device__ __nv_bfloat16 g_w1   [2L*1024*4096];
__device__ __nv_bfloat16 g_w2   [2L*4096*1024];
__device__ __nv_bfloat16 g_qkv  [2L*16384*3072];    // [stream][row][Q|K|V]
__device__ __nv_bfloat16 g_Pmat [1024L*256*256];
__device__ __nv_bfloat16 g_Omat [2L*16384*1024];
__device__ float         g_att  [2L*16384*1024];
__device__ __nv_bfloat16 g_attln[2L*16384*1024];
__device__ __nv_bfloat16 g_hid  [2L*16384*4096];

// ---------------- helpers ----------------
__device__ __forceinline__ uint32_t smem_u32(const void* p) {
    uint32_t a;
    asm("{ .reg .u64 t; cvta.to.shared.u64 t, %1; cvt.u32.u64 %0, t; }" : "=r"(a) : "l"(p));
    return a;
}
__device__ __forceinline__ void cpa16(uint32_t d, const void* s) {
    asm volatile("cp.async.cg.shared.global [%0], [%1], 16;" :: "r"(d), "l"(s));
}
#define CP_COMMIT() asm volatile("cp.async.commit_group;" ::: "memory")

// ---------------- fused convert (6 plain regions) ----------------
struct CvtP {
    const float* s[6];
    __nv_bfloat16* d[6];
    long n[6];
};
__global__ void cvt6_k(CvtP p) {
    int reg = blockIdx.y;
    long i = (long)blockIdx.x * 1024 + threadIdx.x;
    const float* s = p.s[reg];
    __nv_bfloat16* d = p.d[reg];
    long n = p.n[reg];
#pragma unroll
    for (int it = 0; it < 4; ++it) {
        long j = i + (long)it * 256;
        if (j < n) d[j] = __float2bfloat16(s[j]);
    }
}

// qkv weights: [3][1024][1024] per stream -> interleaved [1024][3*1024]
__global__ void cvtqkv_k(const float* __restrict__ wv, const float* __restrict__ wi,
                         __nv_bfloat16* __restrict__ d) {
    const float* s = blockIdx.y ? wi : wv;
    __nv_bfloat16* ds = d + (long)blockIdx.y * 3145728L;
    long idx = (long)blockIdx.x * 256 + threadIdx.x;
    if (idx < 3145728L) {
        int t   = (int)(idx >> 20);
        int rem = (int)(idx & 1048575);
        int kk  = rem >> 10;
        int n   = rem & 1023;
        ds[(long)kk*3072 + t*1024 + n] = __float2bfloat16(s[idx]);
    }
}

// ---------------- fused dual LayerNorm ----------------
__global__ void ln2_k(const float* __restrict__ x0, __nv_bfloat16* __restrict__ y0,
                      const float* __restrict__ g0, const float* __restrict__ b0,
                      const float* __restrict__ x1, __nv_bfloat16* __restrict__ y1,
                      const float* __restrict__ g1, const float* __restrict__ b1) {
    const float* x = blockIdx.y ? x1 : x0;
    __nv_bfloat16* y = blockIdx.y ? y1 : y0;
    const float* gam = blockIdx.y ? g1 : g0;
    const float* bet = blockIdx.y ? b1 : b0;
    long row = blockIdx.x;
    const float* xr = x + row * 1024;
    int tid = threadIdx.x;
    float v[4]; float s = 0.f, s2 = 0.f;
#pragma unroll
    for (int i = 0; i < 4; i++) { float t = xr[tid + i*256]; v[i] = t; s += t; s2 += t*t; }
#pragma unroll
    for (int o = 16; o; o >>= 1) {
        s  += __shfl_xor_sync(0xffffffffu, s,  o);
        s2 += __shfl_xor_sync(0xffffffffu, s2, o);
    }
    __shared__ float sh[2][8];
    if ((tid & 31) == 0) { sh[0][tid>>5] = s; sh[1][tid>>5] = s2; }
    __syncthreads();
    float S = 0.f, S2 = 0.f;
#pragma unroll
    for (int w = 0; w < 8; w++) { S += sh[0][w]; S2 += sh[1][w]; }
    float m   = S  * (1.f/1024.f);
    float var = S2 * (1.f/1024.f) - m*m;
    float inv = rsqrtf(var + 1e-5f);
#pragma unroll
    for (int i = 0; i < 4; i++) {
        int c = tid + i*256;
        y[row*1024 + c] = __float2bfloat16((v[i]-m)*inv*gam[c] + bet[c]);
    }
}

// ---------------- fused scores + softmax: P = softmax(Q K^T * alpha) ----------------
// grid (2 row-tiles, 512 bh, 2 dir), 256 threads
static const int SC_LD   = 136;                   // A/B smem stride (elems)
static const int SC_A_B  = 128 * SC_LD * 2;       // 34816
static const int SC_B_B  = 256 * SC_LD * 2;       // 69632
static const int SC_EPW  = 264;
static const int SC_SMEM = (128 * SC_EPW * 4) > (SC_A_B + SC_B_B)
                         ? (128 * SC_EPW * 4) : (SC_A_B + SC_B_B);   // 135168

__global__ void __launch_bounds__(256) sattn_k(const __nv_bfloat16* __restrict__ qkv,
                                               __nv_bfloat16* __restrict__ Pb) {
    extern __shared__ char dsm[];
    __nv_bfloat16* As = (__nv_bfloat16*)dsm;
    __nv_bfloat16* Bs = (__nv_bfloat16*)(dsm + SC_A_B);
    float* ep = (float*)dsm;

    const int tid = threadIdx.x, warp = tid >> 5, lane = tid & 31;
    const int wm = warp >> 2, wn = warp & 3;
    const int row0 = blockIdx.x * 128;
    const int bh   = blockIdx.y;
    const int dir  = blockIdx.z;
    const int b = bh >> 3, h = bh & 7;
    const int qs = dir ? 0 : 1;
    const int ks = dir ? 1 : 0;
    const long QS = 16384L * 3072;

    const __nv_bfloat16* Qp = qkv + (long)qs*QS + (long)b*786432 + h*128;
    const __nv_bfloat16* Kp = qkv + (long)ks*QS + (long)b*786432 + h*128 + 1024;
    __nv_bfloat16* Cp = Pb + (long)dir*33554432L + (long)b*524288 + (long)h*65536;

    const uint32_t asb = smem_u32(dsm);
    const uint32_t bsb = asb + SC_A_B;

    // load Q tile 128x128 and K 256x128 (16B chunks)
#pragma unroll
    for (int it = 0; it < 8; ++it) {
        int id = tid + it*256;
        int r = id >> 4, c = id & 15;
        cpa16(asb + r*(SC_LD*2) + c*16, Qp + (long)(row0 + r)*3072 + c*8);
    }
#pragma unroll
    for (int it = 0; it < 16; ++it) {
        int id = tid + it*256;
        int r = id >> 4, c = id & 15;
        cpa16(bsb + r*(SC_LD*2) + c*16, Kp + (long)r*3072 + c*8);
    }
    CP_COMMIT();
    asm volatile("cp.async.wait_group 0;" ::: "memory");
    __syncthreads();

    // S = Q @ K^T : warp tile 64x64, full K=128
    wmma::fragment<wmma::accumulator, 16, 16, 16, float> acc[4][4];
#pragma unroll
    for (int i = 0; i < 4; i++)
#pragma unroll
        for (int j = 0; j < 4; j++) wmma::fill_fragment(acc[i][j], 0.f);

#pragma unroll
    for (int kk = 0; kk < 128; kk += 16) {
        wmma::fragment<wmma::matrix_a, 16, 16, 16, __nv_bfloat16, wmma::row_major> fa[4];
        wmma::fragment<wmma::matrix_b, 16, 16, 16, __nv_bfloat16, wmma::col_major> fb[4];
#pragma unroll
        for (int mi = 0; mi < 4; ++mi)
            wmma::load_matrix_sync(fa[mi], &As[(wm*64 + mi*16)*SC_LD + kk], SC_LD);
#pragma unroll
        for (int ni = 0; ni < 4; ++ni)
            wmma::load_matrix_sync(fb[ni], &Bs[(wn*64 + ni*16)*SC_LD + kk], SC_LD);
#pragma unroll
        for (int mi = 0; mi < 4; ++mi)
#pragma unroll
            for (int ni = 0; ni < 4; ++ni)
                wmma::mma_sync(acc[mi][ni], fa[mi], fb[ni], acc[mi][ni]);
    }
    __syncthreads();   // smem tiles dead; reuse for fp32 staging

#pragma unroll
    for (int mi = 0; mi < 4; ++mi)
#pragma unroll
        for (int ni = 0; ni < 4; ++ni)
            wmma::store_matrix_sync(&ep[(wm*64 + mi*16)*SC_EPW + wn*64 + ni*16],
                                    acc[mi][ni], SC_EPW, wmma::mem_row_major);
    __syncthreads();

    // softmax: 16 rows per warp, 256 cols
    const float alpha = 0.08838834764831845f;
#pragma unroll
    for (int rr = 0; rr < 16; ++rr) {
        int r = warp*16 + rr;
        float v[8]; float mx = -1e30f;
#pragma unroll
        for (int e = 0; e < 8; ++e) {
            v[e] = ep[r*SC_EPW + e*32 + lane] * alpha;
            mx = fmaxf(mx, v[e]);
        }
#pragma unroll
        for (int o = 16; o; o >>= 1) mx = fmaxf(mx, __shfl_xor_sync(0xffffffffu, mx, o));
        float s = 0.f;
#pragma unroll
        for (int e = 0; e < 8; ++e) { v[e] = __expf(v[e] - mx); s += v[e]; }
#pragma unroll
        for (int o = 16; o; o >>= 1) s += __shfl_xor_sync(0xffffffffu, s, o);
        float inv = 1.f / s;
#pragma unroll
        for (int e = 0; e < 8; ++e)
            Cp[(long)(row0 + r)*256 + e*32 + lane] = __float2bfloat16(v[e] * inv);
    }
}

// ---------------- GEMM params ----------------
struct GP {
    const __nv_bfloat16* A;
    const __nv_bfloat16* B;
    const __nv_bfloat16* B2;      // second-half weights (M-merged launches)
    void* C;
    const float* bias;
    const float* bias2;
    const float* resid;
    const float* resid2;
    long lda, ldb, ldc, ldr;
    long sAb, sAh, sBb, sBh, sCb, sCh;
    int  Hh;
    int  K;
    int  Msplit;                  // 0 = no M split
    const float* coeffs; int ci0, ci1, ci0b, ci1b;
    float alpha;
};

// ---------------- pipelined wmma GEMM: 256 thr, BK=64, reg double-buffered ----------------
// EPI: 0 = bf16 store (+opt bias), 3 = fp32 c_res*resid + c_out*(acc+bias), 4 = bf16 gelu(acc+bias)
static const int BM = 128, BN = 128, BK = 64;
static const int STG = 3;
static const int LDA_S  = BK + 8;        // 72 elems = 144 B
static const int LDB_NN = BN + 8;        // 136 elems = 272 B
static const int EPW    = 132;           // full-tile epilogue staging stride (fp32)
static const int A_STG_B   = BM * LDA_S * 2;      // 18432 B
static const int B_STG_NN  = BK * LDB_NN * 2;     // 17408 B
static const int SMEM_NN   = STG * (A_STG_B + B_STG_NN);  // 107520

template <int EPI>
__global__ void __launch_bounds__(256) gemm_k(GP p) {
    extern __shared__ char dsm[];
    const int tid  = threadIdx.x;
    const int warp = tid >> 5;
    const int wm = warp >> 2, wn = warp & 3;   // 2x4 warp grid, 64x32 warp tile

    const int z  = blockIdx.z;
    const int bb = z / p.Hh, hh = z - bb * p.Hh;
    const int row0 = blockIdx.y * BM;
    const int col0 = blockIdx.x * BN;

    // instance selection for M-merged launches (uniform branch)
    const __nv_bfloat16* Bsel = p.B;
    const float* bias  = p.bias;
    const float* resid = p.resid;
    int ci0 = p.ci0, ci1 = p.ci1;
    if (p.Msplit && row0 >= p.Msplit) {
        Bsel = p.B2;
        bias = p.bias2;
        if (p.resid2) resid = p.resid2 - (long)p.Msplit * p.ldr;
        ci0 = p.ci0b; ci1 = p.ci1b;
    }

    const __nv_bfloat16* Ab = p.A + (long)bb * p.sAb + (long)hh * p.sAh;
    const __nv_bfloat16* Bb = Bsel + (long)bb * p.sBb + (long)hh * p.sBh;
    const long coff = (long)bb * p.sCb + (long)hh * p.sCh;
    const long lda = p.lda, ldb = p.ldb;

    const uint32_t asb = smem_u32(dsm);
    const uint32_t bsb = asb + STG * A_STG_B;
    __nv_bfloat16* As = (__nv_bfloat16*)dsm;
    __nv_bfloat16* Bs = (__nv_bfloat16*)(dsm + STG * A_STG_B);

    auto load_stage = [&](int slot, int k0) {
        uint32_t ab = asb + slot * A_STG_B;
#pragma unroll
        for (int it = 0; it < 4; ++it) {
            int id = tid + it*256;
            int r = id >> 3, c = id & 7;
            cpa16(ab + r*144 + c*16, Ab + (long)(row0 + r)*lda + k0 + c*8);
        }
        uint32_t bbp = bsb + slot * B_STG_NN;
#pragma unroll
        for (int it = 0; it < 4; ++it) {
            int id = tid + it*256;
            int r = id >> 4, c = id & 15;
            cpa16(bbp + r*272 + c*16, Bb + (long)(k0 + r)*ldb + col0 + c*8);
        }
    };

    wmma::fragment<wmma::accumulator, 16, 16, 16, float> acc[4][2];
#pragma unroll
    for (int i = 0; i < 4; i++)
#pragma unroll
        for (int j = 0; j < 2; j++) wmma::fill_fragment(acc[i][j], 0.f);

    wmma::fragment<wmma::matrix_a, 16, 16, 16, __nv_bfloat16, wmma::row_major> fa[2][4];
    wmma::fragment<wmma::matrix_b, 16, 16, 16, __nv_bfloat16, wmma::row_major> fbr[2][2];

    const int kiters = p.K >> 6;

#pragma unroll
    for (int s = 0; s < STG-1; ++s) {
        if (s < kiters) load_stage(s, s * BK);
        CP_COMMIT();
    }

    for (int k = 0; k < kiters; ++k) {
        asm volatile("cp.async.wait_group %0;" :: "n"(STG-2));
        __syncthreads();
        int pf = k + STG - 1;
        if (pf < kiters) load_stage(pf % STG, pf * BK);
        CP_COMMIT();

        int slot = k % STG;
        __nv_bfloat16* Asl = As + slot * (BM * LDA_S);
        __nv_bfloat16* BslNN = Bs + slot * (BK * LDB_NN);

#pragma unroll
        for (int mi = 0; mi < 4; ++mi)
            wmma::load_matrix_sync(fa[0][mi], &Asl[(wm*64 + mi*16)*LDA_S + 0], LDA_S);
#pragma unroll
        for (int ni = 0; ni < 2; ++ni)
            wmma::load_matrix_sync(fbr[0][ni], &BslNN[0*LDB_NN + wn*32 + ni*16], LDB_NN);

#pragma unroll
        for (int j = 0; j < 4; ++j) {
            int cur = j & 1, nxt = cur ^ 1;
            if (j < 3) {
                int kk = (j + 1) * 16;
#pragma unroll
                for (int mi = 0; mi < 4; ++mi)
                    wmma::load_matrix_sync(fa[nxt][mi], &Asl[(wm*64 + mi*16)*LDA_S + kk], LDA_S);
#pragma unroll
                for (int ni = 0; ni < 2; ++ni)
                    wmma::load_matrix_sync(fbr[nxt][ni], &BslNN[kk*LDB_NN + wn*32 + ni*16], LDB_NN);
            }
#pragma unroll
            for (int mi = 0; mi < 4; ++mi)
#pragma unroll
                for (int ni = 0; ni < 2; ++ni)
                    wmma::mma_sync(acc[mi][ni], fa[cur][mi], fbr[cur][ni], acc[mi][ni]);
        }
    }
    __syncthreads();   // mainloop smem is dead; reuse dsm for epilogue staging

    // ---------------- one-shot full-tile epilogue ----------------
    float* ep = (float*)dsm;   // 128 x EPW fp32 tile
#pragma unroll
    for (int mi = 0; mi < 4; ++mi)
#pragma unroll
        for (int ni = 0; ni < 2; ++ni)
            wmma::store_matrix_sync(&ep[(wm*64 + mi*16)*EPW + wn*32 + ni*16],
                                    acc[mi][ni], EPW, wmma::mem_row_major);
    __syncthreads();

    float c_res = 0.f, c_out = 0.f;
    if (EPI == 3) { c_res = p.coeffs[ci0]; c_out = p.coeffs[ci1]; }
    const int tr  = tid >> 5;    // 0..7
    const int tc4 = tid & 31;    // 0..31 (float4 column index)
    const int gc  = col0 + tc4 * 4;
#pragma unroll
    for (int it = 0; it < 16; ++it) {
        int r = tr + it * 8;
        long gr = row0 + r;
        float4 v4 = *(float4*)&ep[r * EPW + tc4 * 4];
        long cidx = coff + gr * p.ldc + gc;
        if (EPI == 0) {
            if (bias) {
                float4 b4 = *(const float4*)&bias[gc];
                v4.x += b4.x; v4.y += b4.y; v4.z += b4.z; v4.w += b4.w;
            }
            __nv_bfloat162 h0 = __floats2bfloat162_rn(v4.x, v4.y);
            __nv_bfloat162 h1 = __floats2bfloat162_rn(v4.z, v4.w);
            uint2 u;
            u.x = *(uint32_t*)&h0; u.y = *(uint32_t*)&h1;
            *(uint2*)&((__nv_bfloat16*)p.C)[cidx] = u;
        } else if (EPI == 3) {
            float4 b4 = *(const float4*)&bias[gc];
            float4 r4 = *(const float4*)&resid[gr * p.ldr + gc];
            float4 o4;
            o4.x = c_res * r4.x + c_out * (v4.x + b4.x);
            o4.y = c_res * r4.y + c_out * (v4.y + b4.y);
            o4.z = c_res * r4.z + c_out * (v4.z + b4.z);
            o4.w = c_res * r4.w + c_out * (v4.w + b4.w);
            *(float4*)&((float*)p.C)[cidx] = o4;
        } else if (EPI == 4) {
            float4 b4 = *(const float4*)&bias[gc];
            v4.x += b4.x; v4.y += b4.y; v4.z += b4.z; v4.w += b4.w;
            const float is2 = 0.70710678118654752f;
            float g0 = 0.5f * v4.x * (1.f + erff(v4.x * is2));
            float g1 = 0.5f * v4.y * (1.f + erff(v4.y * is2));
            float g2 = 0.5f * v4.z * (1.f + erff(v4.z * is2));
            float g3 = 0.5f * v4.w * (1.f + erff(v4.w * is2));
            __nv_bfloat162 h0 = __floats2bfloat162_rn(g0, g1);
            __nv_bfloat162 h1 = __floats2bfloat162_rn(g2, g3);
            uint2 u;
            u.x = *(uint32_t*)&h0; u.y = *(uint32_t*)&h1;
            *(uint2*)&((__nv_bfloat16*)p.C)[cidx] = u;
        }
    }
}

// ---------------- host orchestration ----------------
extern "C" void kernel_launch(void* const* d_in, const int* in_sizes, int n_in,
                              void* d_out, int out_size) {
    (void)in_sizes; (void)n_in; (void)out_size;
    const float* rgb    = (const float*)d_in[0];
    const float* irp    = (const float*)d_in[1];
    const float* ln1g   = (const float*)d_in[2];
    const float* ln1b   = (const float*)d_in[3];
    const float* ln2g   = (const float*)d_in[4];
    const float* ln2b   = (const float*)d_in[5];
    const float* Wqkv_v = (const float*)d_in[6];
    const float* bqkv_v = (const float*)d_in[7];
    const float* Wqkv_i = (const float*)d_in[8];
    const float* bqkv_i = (const float*)d_in[9];
    const float* Wo_v   = (const float*)d_in[10];
    const float* bo_v   = (const float*)d_in[11];
    const float* Wo_i   = (const float*)d_in[12];
    const float* bo_i   = (const float*)d_in[13];
    const float* blng   = (const float*)d_in[14];
    const float* blnb   = (const float*)d_in[15];
    const float* W1_v   = (const float*)d_in[16];
    const float* b1_v   = (const float*)d_in[17];
    const float* W2_v   = (const float*)d_in[18];
    const float* b2_v   = (const float*)d_in[19];
    const float* W1_i   = (const float*)d_in[20];
    const float* b1_i   = (const float*)d_in[21];
    const float* W2_i   = (const float*)d_in[22];
    const float* b2_i   = (const float*)d_in[23];
    const float* coef   = (const float*)d_in[24];
    float* out = (float*)d_out;

    __nv_bfloat16 *xln, *wqkv, *wo, *w1, *w2, *qkv, *Pb, *Ob, *attln, *hb;
    float *attb;
    cudaGetSymbolAddress((void**)&xln,   g_xln);
    cudaGetSymbolAddress((void**)&wqkv,  g_wqkv);
    cudaGetSymbolAddress((void**)&wo,    g_wo);
    cudaGetSymbolAddress((void**)&w1,    g_w1);
    cudaGetSymbolAddress((void**)&w2,    g_w2);
    cudaGetSymbolAddress((void**)&qkv,   g_qkv);
    cudaGetSymbolAddress((void**)&Pb,    g_Pmat);
    cudaGetSymbolAddress((void**)&Ob,    g_Omat);
    cudaGetSymbolAddress((void**)&attb,  g_att);
    cudaGetSymbolAddress((void**)&attln, g_attln);
    cudaGetSymbolAddress((void**)&hb,    g_hid);

    cudaFuncSetAttribute(gemm_k<0>, cudaFuncAttributeMaxDynamicSharedMemorySize, SMEM_NN);
    cudaFuncSetAttribute(gemm_k<3>, cudaFuncAttributeMaxDynamicSharedMemorySize, SMEM_NN);
    cudaFuncSetAttribute(gemm_k<4>, cudaFuncAttributeMaxDynamicSharedMemorySize, SMEM_NN);
    cudaFuncSetAttribute(sattn_k,   cudaFuncAttributeMaxDynamicSharedMemorySize, SC_SMEM);

    const long QS = 16384L * 3072;   // qkv stream stride

    // weights -> bf16: qkv interleaved + 6 plain regions
    cvtqkv_k<<<dim3(12288, 2), 256>>>(Wqkv_v, Wqkv_i, wqkv);
    {
        CvtP cp{};
        cp.s[0] = Wo_v; cp.d[0] = wo;            cp.n[0] = 1048576L;
        cp.s[1] = Wo_i; cp.d[1] = wo + 1048576L; cp.n[1] = 1048576L;
        cp.s[2] = W1_v; cp.d[2] = w1;            cp.n[2] = 4194304L;
        cp.s[3] = W1_i; cp.d[3] = w1 + 4194304L; cp.n[3] = 4194304L;
        cp.s[4] = W2_v; cp.d[4] = w2;            cp.n[4] = 4194304L;
        cp.s[5] = W2_i; cp.d[5] = w2 + 4194304L; cp.n[5] = 4194304L;
        cvt6_k<<<dim3(4096, 6), 256>>>(cp);
    }

    // input LayerNorms (one launch)
    ln2_k<<<dim3(16384, 2), 256>>>(rgb, xln, ln1g, ln1b,
                                   irp, xln + 16777216L, ln2g, ln2b);

    // QKV: ONE launch, M=32768, N=3072, K=1024
    {
        GP p{};
        p.A = xln;                 p.lda = 1024;
        p.B = wqkv;                p.B2 = wqkv + 3145728L;  p.ldb = 3072;
        p.C = qkv;                 p.ldc = 3072;
        p.bias = bqkv_v;           p.bias2 = bqkv_i;
        p.Msplit = 16384;
        p.Hh = 1; p.K = 1024; p.coeffs = coef;
        gemm_k<0><<<dim3(24, 256, 1), 256, SMEM_NN>>>(p);
    }

    // fused scores + softmax -> P (bf16), one launch
    sattn_k<<<dim3(2, 512, 2), 256, SC_SMEM>>>(qkv, Pb);

    // O = P @ V (batched; V at col offset 2048)
    for (int dir = 0; dir < 2; ++dir) {
        int ks = (dir == 0) ? 0 : 1;
        GP p{};
        p.A = Pb + (long)dir * 33554432L;   p.lda = 256;  p.sAb = 524288; p.sAh = 65536;
        p.B = qkv + (long)ks * QS + 2048;   p.ldb = 3072; p.sBb = 786432; p.sBh = 128;
        p.C = Ob + (long)dir * 16777216L;   p.ldc = 1024; p.sCb = 262144; p.sCh = 128;
        p.bias = nullptr; p.Hh = 8; p.K = 256; p.coeffs = coef;
        gemm_k<0><<<dim3(1, 2, 512), 256, SMEM_NN>>>(p);
    }

    // output projection + residual: ONE launch, M=32768
    {
        GP p{};
        p.A = Ob;                 p.lda = 1024;
        p.B = wo;                 p.B2 = wo + 1048576L;   p.ldb = 1024;
        p.C = attb;               p.ldc = 1024;
        p.bias = bo_v;            p.bias2 = bo_i;
        p.resid = rgb;            p.resid2 = irp;         p.ldr = 1024;
        p.Msplit = 16384;
        p.coeffs = coef; p.ci0 = 0; p.ci1 = 1; p.ci0b = 2; p.ci1b = 3;
        p.Hh = 1; p.K = 1024;
        gemm_k<3><<<dim3(8, 256, 1), 256, SMEM_NN>>>(p);
    }

    // block LayerNorm (one launch, shared gamma/beta)
    ln2_k<<<dim3(16384, 2), 256>>>(attb, attln, blng, blnb,
                                   attb + 16777216L, attln + 16777216L, blng, blnb);

    // MLP layer 1 + exact GELU: ONE launch, M=32768, N=4096, K=1024
    {
        GP p{};
        p.A = attln;              p.lda = 1024;
        p.B = w1;                 p.B2 = w1 + 4194304L;   p.ldb = 4096;
        p.C = hb;                 p.ldc = 4096;
        p.bias = b1_v;            p.bias2 = b1_i;
        p.Msplit = 16384;
        p.Hh = 1; p.K = 1024; p.coeffs = coef;
        gemm_k<4><<<dim3(32, 256, 1), 256, SMEM_NN>>>(p);
    }

    // MLP layer 2 + final combine -> d_out: ONE launch, M=32768, K=4096
    {
        GP p{};
        p.A = hb;                 p.lda = 4096;
        p.B = w2;                 p.B2 = w2 + 4194304L;   p.ldb = 1024;
        p.C = out;                p.ldc = 1024;
        p.bias = b2_v;            p.bias2 = b2_i;
        p.resid = attb;           p.resid2 = nullptr;     p.ldr = 1024;
        p.Msplit = 16384;
        p.coeffs = coef; p.ci0 = 4; p.ci1 = 5; p.ci0b = 6; p.ci1b = 7;
        p.Hh = 1; p.K = 4096;
        gemm_k<3><<<dim3(8, 256, 1), 256, SMEM_NN>>>(p);
    }
}